// round 1
// baseline (speedup 1.0000x reference)
#include <cuda_runtime.h>
#include <cuda_bf16.h>
#include <cstddef>

// Problem constants
#define SS 2048
#define BB 32
#define DD 256
#define HH 4
#define MM (SS * BB)           // 65536 rows
#define SBD (SS * BB * DD)     // 16,777,216 elements
#define EPSV 1e-5f

// ---------------- scratch (no cudaMalloc allowed) ----------------
__device__ float g_qa[SBD];
__device__ float g_qb[SBD];
__device__ float g_ka[SBD];
__device__ float g_kb[SBD];
__device__ float g_va[SBD];
__device__ float g_vb[SBD];
__device__ float g_w1[SBD];
__device__ float g_w2[SBD];
__device__ float g_stats[512];     // [sum(256), sumsq(256)]
__device__ float g_scale[256];
__device__ float g_shift[256];
__device__ float g_xcat[BB * DD * HH];   // [32, 1024]
__device__ float g_m0[BB * DD];
__device__ float g_m1[BB * DD];

// ---------------- GEMM: C[M,256] = act(A)[M,256] @ W[256,256]^T + bias ----------------
// W row-major [n][k]. Optional A transform: a' = relu(a*trs[k] + trb[k]).
// Optional extra output: wout = C - sub (elementwise), used for w = k_new - q_new.
#define TM 64
#define TN 64
#define TKc 16

__global__ __launch_bounds__(256) void gemm_k(
    const float* __restrict__ A, const float* __restrict__ W,
    const float* __restrict__ bias, float* __restrict__ C,
    const float* __restrict__ trs, const float* __restrict__ trb,
    const float* __restrict__ sub, float* __restrict__ wout)
{
    __shared__ float As[TKc][TM];
    __shared__ float Ws[TKc][TN];

    const int tid = threadIdx.x;           // 0..255
    const int tx = tid & 15;               // col group
    const int ty = tid >> 4;               // row group
    const int row0 = blockIdx.y * TM;
    const int col0 = blockIdx.x * TN;

    const int lr  = tid >> 2;              // 0..63, row within tile for loads
    const int lk4 = (tid & 3) * 4;         // 0,4,8,12

    float acc[4][4];
#pragma unroll
    for (int i = 0; i < 4; i++)
#pragma unroll
        for (int j = 0; j < 4; j++) acc[i][j] = 0.f;

    for (int k0 = 0; k0 < DD; k0 += TKc) {
        // load A tile (64 rows x 16 k), transposed into smem
        float4 a4 = *(const float4*)(A + (size_t)(row0 + lr) * DD + k0 + lk4);
        if (trs != nullptr) {
            a4.x = fmaxf(fmaf(a4.x, trs[k0 + lk4 + 0], trb[k0 + lk4 + 0]), 0.f);
            a4.y = fmaxf(fmaf(a4.y, trs[k0 + lk4 + 1], trb[k0 + lk4 + 1]), 0.f);
            a4.z = fmaxf(fmaf(a4.z, trs[k0 + lk4 + 2], trb[k0 + lk4 + 2]), 0.f);
            a4.w = fmaxf(fmaf(a4.w, trs[k0 + lk4 + 3], trb[k0 + lk4 + 3]), 0.f);
        }
        As[lk4 + 0][lr] = a4.x;
        As[lk4 + 1][lr] = a4.y;
        As[lk4 + 2][lr] = a4.z;
        As[lk4 + 3][lr] = a4.w;

        // load W tile (64 n x 16 k), transposed into smem
        float4 w4 = *(const float4*)(W + (size_t)(col0 + lr) * DD + k0 + lk4);
        Ws[lk4 + 0][lr] = w4.x;
        Ws[lk4 + 1][lr] = w4.y;
        Ws[lk4 + 2][lr] = w4.z;
        Ws[lk4 + 3][lr] = w4.w;

        __syncthreads();

#pragma unroll
        for (int k = 0; k < TKc; k++) {
            float4 av = *(const float4*)&As[k][ty * 4];
            float4 wv = *(const float4*)&Ws[k][tx * 4];
            acc[0][0] = fmaf(av.x, wv.x, acc[0][0]);
            acc[0][1] = fmaf(av.x, wv.y, acc[0][1]);
            acc[0][2] = fmaf(av.x, wv.z, acc[0][2]);
            acc[0][3] = fmaf(av.x, wv.w, acc[0][3]);
            acc[1][0] = fmaf(av.y, wv.x, acc[1][0]);
            acc[1][1] = fmaf(av.y, wv.y, acc[1][1]);
            acc[1][2] = fmaf(av.y, wv.z, acc[1][2]);
            acc[1][3] = fmaf(av.y, wv.w, acc[1][3]);
            acc[2][0] = fmaf(av.z, wv.x, acc[2][0]);
            acc[2][1] = fmaf(av.z, wv.y, acc[2][1]);
            acc[2][2] = fmaf(av.z, wv.z, acc[2][2]);
            acc[2][3] = fmaf(av.z, wv.w, acc[2][3]);
            acc[3][0] = fmaf(av.w, wv.x, acc[3][0]);
            acc[3][1] = fmaf(av.w, wv.y, acc[3][1]);
            acc[3][2] = fmaf(av.w, wv.z, acc[3][2]);
            acc[3][3] = fmaf(av.w, wv.w, acc[3][3]);
        }
        __syncthreads();
    }

    const int cb = col0 + tx * 4;
    const float b0 = bias[cb + 0], b1 = bias[cb + 1], b2 = bias[cb + 2], b3 = bias[cb + 3];
#pragma unroll
    for (int i = 0; i < 4; i++) {
        const size_t r = (size_t)(row0 + ty * 4 + i);
        float4 o;
        o.x = acc[i][0] + b0;
        o.y = acc[i][1] + b1;
        o.z = acc[i][2] + b2;
        o.w = acc[i][3] + b3;
        *(float4*)(C + r * DD + cb) = o;
        if (wout != nullptr) {
            float4 s = *(const float4*)(sub + r * DD + cb);
            float4 w;
            w.x = o.x - s.x; w.y = o.y - s.y; w.z = o.z - s.z; w.w = o.w - s.w;
            *(float4*)(wout + r * DD + cb) = w;
        }
    }
}

// ---------------- BatchNorm stats ----------------
__global__ void zero_stats_k(float* stats) { stats[threadIdx.x] = 0.f; }

__global__ __launch_bounds__(256) void bn_reduce_k(const float* __restrict__ x,
                                                   float* __restrict__ stats)
{
    const int c = threadIdx.x;
    const int r0 = blockIdx.x * 256;
    float s = 0.f, q = 0.f;
    for (int r = r0; r < r0 + 256; r++) {
        float v = x[(size_t)r * DD + c];
        s += v;
        q = fmaf(v, v, q);
    }
    atomicAdd(&stats[c], s);
    atomicAdd(&stats[256 + c], q);
}

__global__ void bn_finalize_k(const float* __restrict__ stats,
                              const float* __restrict__ gamma,
                              const float* __restrict__ beta,
                              float* __restrict__ scale, float* __restrict__ shift)
{
    const int c = threadIdx.x;
    const float invM = 1.0f / (float)MM;
    float mean = stats[c] * invM;
    float var = stats[256 + c] * invM - mean * mean;
    float sc = gamma[c] * rsqrtf(var + EPSV);
    scale[c] = sc;
    shift[c] = beta[c] - mean * sc;
}

// ---------------- fused softmax(seq) * v sum ----------------
// w, v: [S, B*D] (row-major, stride 8192). out: xcat[b*1024 + head*256 + d].
__global__ __launch_bounds__(256) void softmax_wv_k(const float* __restrict__ w,
                                                    const float* __restrict__ v,
                                                    float* __restrict__ xcat, int head)
{
    const int c = blockIdx.x * 32 + threadIdx.x;   // column 0..8191
    const int ty = threadIdx.y;                    // 0..7
    float m = -1e30f, l = 0.f, a = 0.f;
    for (int s = ty; s < SS; s += 8) {
        const size_t idx = (size_t)s * (BB * DD) + c;
        float x = w[idx];
        float val = v[idx];
        float nm = fmaxf(m, x);
        float corr = __expf(m - nm);
        float e = __expf(x - nm);
        l = l * corr + e;
        a = a * corr + e * val;
        m = nm;
    }
    __shared__ float sm[8][32], sl[8][32], sa[8][32];
    sm[ty][threadIdx.x] = m;
    sl[ty][threadIdx.x] = l;
    sa[ty][threadIdx.x] = a;
    __syncthreads();
    if (ty == 0) {
        for (int j = 1; j < 8; j++) {
            float m2 = sm[j][threadIdx.x], l2 = sl[j][threadIdx.x], a2 = sa[j][threadIdx.x];
            float nm = fmaxf(m, m2);
            float c1 = __expf(m - nm), c2 = __expf(m2 - nm);
            l = l * c1 + l2 * c2;
            a = a * c1 + a2 * c2;
            m = nm;
        }
        int b = c >> 8, d = c & 255;
        xcat[b * (DD * HH) + head * DD + d] = a / l;
    }
}

// ---------------- tiny final MLP layer ----------------
// y[b, n] = (relu?)(x[b, :K] dot Wt[n, :K] + bias[n]); grid=B, block=256
__global__ __launch_bounds__(256) void mlp_k(const float* __restrict__ x,
                                             const float* __restrict__ Wt,
                                             const float* __restrict__ bias,
                                             float* __restrict__ y, int K, int do_relu)
{
    __shared__ float xs[1024];
    const int b = blockIdx.x;
    for (int i = threadIdx.x; i < K; i += 256) xs[i] = x[b * K + i];
    __syncthreads();
    const int n = threadIdx.x;
    float acc = bias[n];
    const float* wr = Wt + (size_t)n * K;
    for (int k = 0; k < K; k++) acc = fmaf(xs[k], wr[k], acc);
    if (do_relu) acc = fmaxf(acc, 0.f);
    y[b * DD + n] = acc;
}

// ---------------- driver ----------------
static float* sym(const void* s)
{
    void* p = nullptr;
    cudaGetSymbolAddress(&p, (const void*)s);
    return (float*)p;
}

extern "C" void kernel_launch(void* const* d_in, const int* in_sizes, int n_in,
                              void* d_out, int out_size)
{
    (void)in_sizes; (void)n_in; (void)out_size;
    // metadata order == setup_inputs dict order
    const float* q_in = (const float*)d_in[0];
    const float* k_in = (const float*)d_in[1];
    const float* v_in = (const float*)d_in[2];
    const float* wq = (const float*)d_in[3];
    const float* bq = (const float*)d_in[4];
    const float* wk = (const float*)d_in[5];
    const float* bk = (const float*)d_in[6];
    const float* wv = (const float*)d_in[7];
    const float* bv = (const float*)d_in[8];
    const float* g1 = (const float*)d_in[9];
    const float* be1 = (const float*)d_in[10];
    const float* wl1 = (const float*)d_in[11];
    const float* bl1 = (const float*)d_in[12];
    const float* g2 = (const float*)d_in[13];
    const float* be2 = (const float*)d_in[14];
    const float* wl2 = (const float*)d_in[15];
    const float* bl2 = (const float*)d_in[16];
    const float* mw0 = (const float*)d_in[17];
    const float* mb0 = (const float*)d_in[18];
    const float* mw1 = (const float*)d_in[19];
    const float* mb1 = (const float*)d_in[20];
    const float* mw2 = (const float*)d_in[21];
    const float* mb2 = (const float*)d_in[22];

    float* qa = sym(g_qa); float* qb = sym(g_qb);
    float* ka = sym(g_ka); float* kb = sym(g_kb);
    float* va = sym(g_va); float* vb = sym(g_vb);
    float* w1 = sym(g_w1); float* w2 = sym(g_w2);
    float* stats = sym(g_stats);
    float* scale = sym(g_scale);
    float* shift = sym(g_shift);
    float* xcat = sym(g_xcat);
    float* m0 = sym(g_m0);
    float* m1 = sym(g_m1);

    const dim3 gg(DD / TN, MM / TM);   // (4, 1024)
    const dim3 gb(256);

    const float* qs = q_in; const float* ks = k_in; const float* vs = v_in;
    float* qpp[2] = { qa, qb };
    float* kpp[2] = { ka, kb };
    float* vpp[2] = { va, vb };

    for (int h = 0; h < HH; h++) {
        float* qd = qpp[h & 1];
        float* kd = kpp[h & 1];
        float* vd = vpp[h & 1];
        const float* Wq = wq + (size_t)h * DD * DD;
        const float* Wk = wk + (size_t)h * DD * DD;
        const float* Wv = wv + (size_t)h * DD * DD;

        // q/v projections
        gemm_k<<<gg, gb>>>(qs, Wq, bq + h * DD, qd, nullptr, nullptr, nullptr, nullptr);
        gemm_k<<<gg, gb>>>(vs, Wv, bv + h * DD, vd, nullptr, nullptr, nullptr, nullptr);
        // k projection with fused w = k_new - q_new
        gemm_k<<<gg, gb>>>(ks, Wk, bk + h * DD, kd, nullptr, nullptr, qd, w1);

        // BN1 stats on w1
        zero_stats_k<<<1, 512>>>(stats);
        bn_reduce_k<<<MM / 256, 256>>>(w1, stats);
        bn_finalize_k<<<1, 256>>>(stats, g1 + h * DD, be1 + h * DD, scale, shift);
        // w2 = relu(bn(w1)) @ wl1^T + bl1   (BN+ReLU fused into A-load)
        gemm_k<<<gg, gb>>>(w1, wl1 + (size_t)h * DD * DD, bl1 + h * DD, w2,
                           scale, shift, nullptr, nullptr);

        // BN2 stats on w2
        zero_stats_k<<<1, 512>>>(stats);
        bn_reduce_k<<<MM / 256, 256>>>(w2, stats);
        bn_finalize_k<<<1, 256>>>(stats, g2 + h * DD, be2 + h * DD, scale, shift);
        // w1 = relu(bn(w2)) @ wl2^T + bl2
        gemm_k<<<gg, gb>>>(w2, wl2 + (size_t)h * DD * DD, bl2 + h * DD, w1,
                           scale, shift, nullptr, nullptr);

        // xcat[:, h*256:(h+1)*256] = softmax_s(w1) weighted sum of v
        softmax_wv_k<<<256, dim3(32, 8)>>>(w1, vd, xcat, h);

        qs = qd; ks = kd; vs = vd;
    }

    // final MLP: [32,1024] -> [32,256] -> [32,256] -> [32,256]
    mlp_k<<<BB, 256>>>(xcat, mw0, mb0, m0, DD * HH, 1);
    mlp_k<<<BB, 256>>>(m0, mw1, mb1, m1, DD, 1);
    mlp_k<<<BB, 256>>>(m1, mw2, mb2, (float*)d_out, DD, 0);
}

// round 4
// speedup vs baseline: 2.1336x; 2.1336x over previous
#include <cuda_runtime.h>
#include <cstdint>
#include <cstddef>

// ---------------- problem constants ----------------
#define SS 2048
#define BB 32
#define DD 256
#define HH 4
#define MM (SS * BB)           // 65536 rows
#define SBD (SS * BB * DD)     // 16,777,216 elements
#define EPSV 1e-5f

// ---------------- mma.sync tf32 GEMM config ----------------
#define BLKM 128               // rows per CTA
#define KCH 32                 // K per chunk
#define NCHUNK (DD / KCH)      // 8
#define SA 36                  // A smem row stride (floats): bank = 4g+t bijective
#define SB 44                  // B smem row stride (floats): bank = 12g+t bijective
#define A_BUF_FL (BLKM * SA)   // 4608 floats  (18432 B)
#define B_BUF_FL (DD * SB)     // 11264 floats (45056 B)
#define SMEM_FLOATS (2 * A_BUF_FL + 2 * B_BUF_FL)
#define SMEM_BYTES (SMEM_FLOATS * 4)   // 126976 B

// ---------------- scratch (no cudaMalloc allowed) ----------------
__device__ float g_qa[SBD];
__device__ float g_qb[SBD];
__device__ float g_ka[SBD];
__device__ float g_kb[SBD];
__device__ float g_va[SBD];
__device__ float g_vb[SBD];
__device__ float g_w1[SBD];
__device__ float g_w2[SBD];
__device__ float g_stats[512];
__device__ float g_scale[256];
__device__ float g_shift[256];
__device__ float g_xcat[BB * DD * HH];
__device__ float g_m0[BB * DD];
__device__ float g_m1[BB * DD];

// ---------------- helpers ----------------
__device__ __forceinline__ float f2tf(float x)
{
    uint32_t r;
    asm("cvt.rna.tf32.f32 %0, %1;" : "=r"(r) : "f"(x));
    return __uint_as_float(r);
}

__device__ __forceinline__ void mma_tf32(float* d, uint32_t a0, uint32_t a1,
                                         uint32_t a2, uint32_t a3,
                                         uint32_t b0, uint32_t b1)
{
    asm volatile(
        "mma.sync.aligned.m16n8k8.row.col.f32.tf32.tf32.f32 "
        "{%0,%1,%2,%3}, {%4,%5,%6,%7}, {%8,%9}, {%0,%1,%2,%3};"
        : "+f"(d[0]), "+f"(d[1]), "+f"(d[2]), "+f"(d[3])
        : "r"(a0), "r"(a1), "r"(a2), "r"(a3), "r"(b0), "r"(b1));
}

// ---------------- GEMM: C[M,256] = act(A)[M,256] @ W[256,256]^T + bias ----------------
// optional A transform relu(a*trs+trb); optional wout = C - sub
__global__ __launch_bounds__(512, 1) void gemm_tc(
    const float* __restrict__ A, const float* __restrict__ W,
    const float* __restrict__ bias, float* __restrict__ C,
    const float* __restrict__ trs, const float* __restrict__ trb,
    const float* __restrict__ sub, float* __restrict__ wout)
{
    extern __shared__ float sm[];
    float* const Asm[2] = { sm, sm + A_BUF_FL };
    float* const Bsm[2] = { sm + 2 * A_BUF_FL, sm + 2 * A_BUF_FL + B_BUF_FL };

    const int tid = threadIdx.x;
    const int wid = tid >> 5, lane = tid & 31;
    const int g = lane >> 2, t = lane & 3;
    const int wm = wid >> 3;         // 0..1, 64 rows each
    const int wn = wid & 7;          // 0..7, 32 cols each
    const int row0 = blockIdx.x * BLKM;

    // fill mapping
    const int ar = tid >> 2;                 // 0..127 (A row)
    const int ak = (tid & 3) * 8;            // k sub-offset
    const int bn = tid >> 1;                 // 0..255 (B/W row = n)
    const int bk = (tid & 1) * 16;

    const float* const Arow = A + (size_t)(row0 + ar) * DD + ak;
    const float* const Wrow = W + (size_t)bn * DD + bk;

    float acc[4][4][4];
#pragma unroll
    for (int mt = 0; mt < 4; mt++)
#pragma unroll
        for (int nt = 0; nt < 4; nt++)
#pragma unroll
            for (int j = 0; j < 4; j++) acc[mt][nt][j] = 0.f;

    float4 pa0, pa1, pb0, pb1, pb2, pb3;

    // ---- prefetch + transform chunk 0 ----
    {
        float4 v0 = *(const float4*)(Arow);
        float4 v1 = *(const float4*)(Arow + 4);
        if (trs != nullptr) {
            float4 s0 = *(const float4*)(trs + ak);
            float4 s1 = *(const float4*)(trs + ak + 4);
            float4 c0 = *(const float4*)(trb + ak);
            float4 c1 = *(const float4*)(trb + ak + 4);
            v0.x = fmaxf(fmaf(v0.x, s0.x, c0.x), 0.f);
            v0.y = fmaxf(fmaf(v0.y, s0.y, c0.y), 0.f);
            v0.z = fmaxf(fmaf(v0.z, s0.z, c0.z), 0.f);
            v0.w = fmaxf(fmaf(v0.w, s0.w, c0.w), 0.f);
            v1.x = fmaxf(fmaf(v1.x, s1.x, c1.x), 0.f);
            v1.y = fmaxf(fmaf(v1.y, s1.y, c1.y), 0.f);
            v1.z = fmaxf(fmaf(v1.z, s1.z, c1.z), 0.f);
            v1.w = fmaxf(fmaf(v1.w, s1.w, c1.w), 0.f);
        }
        pa0.x = f2tf(v0.x); pa0.y = f2tf(v0.y); pa0.z = f2tf(v0.z); pa0.w = f2tf(v0.w);
        pa1.x = f2tf(v1.x); pa1.y = f2tf(v1.y); pa1.z = f2tf(v1.z); pa1.w = f2tf(v1.w);
        float4 w0 = *(const float4*)(Wrow);
        float4 w1 = *(const float4*)(Wrow + 4);
        float4 w2 = *(const float4*)(Wrow + 8);
        float4 w3 = *(const float4*)(Wrow + 12);
        pb0.x = f2tf(w0.x); pb0.y = f2tf(w0.y); pb0.z = f2tf(w0.z); pb0.w = f2tf(w0.w);
        pb1.x = f2tf(w1.x); pb1.y = f2tf(w1.y); pb1.z = f2tf(w1.z); pb1.w = f2tf(w1.w);
        pb2.x = f2tf(w2.x); pb2.y = f2tf(w2.y); pb2.z = f2tf(w2.z); pb2.w = f2tf(w2.w);
        pb3.x = f2tf(w3.x); pb3.y = f2tf(w3.y); pb3.z = f2tf(w3.z); pb3.w = f2tf(w3.w);
    }
    {
        float* ad = Asm[0] + ar * SA + ak;
        *(float4*)ad = pa0;
        *(float4*)(ad + 4) = pa1;
        float* bd = Bsm[0] + bn * SB + bk;
        *(float4*)bd = pb0;
        *(float4*)(bd + 4) = pb1;
        *(float4*)(bd + 8) = pb2;
        *(float4*)(bd + 12) = pb3;
    }
    __syncthreads();

#pragma unroll 1
    for (int i = 0; i < NCHUNK; i++) {
        const int b = i & 1;

        // prefetch next chunk into regs (overlaps with mma below)
        if (i + 1 < NCHUNK) {
            const int k0 = (i + 1) * KCH;
            float4 v0 = *(const float4*)(Arow + k0);
            float4 v1 = *(const float4*)(Arow + k0 + 4);
            if (trs != nullptr) {
                float4 s0 = *(const float4*)(trs + k0 + ak);
                float4 s1 = *(const float4*)(trs + k0 + ak + 4);
                float4 c0 = *(const float4*)(trb + k0 + ak);
                float4 c1 = *(const float4*)(trb + k0 + ak + 4);
                v0.x = fmaxf(fmaf(v0.x, s0.x, c0.x), 0.f);
                v0.y = fmaxf(fmaf(v0.y, s0.y, c0.y), 0.f);
                v0.z = fmaxf(fmaf(v0.z, s0.z, c0.z), 0.f);
                v0.w = fmaxf(fmaf(v0.w, s0.w, c0.w), 0.f);
                v1.x = fmaxf(fmaf(v1.x, s1.x, c1.x), 0.f);
                v1.y = fmaxf(fmaf(v1.y, s1.y, c1.y), 0.f);
                v1.z = fmaxf(fmaf(v1.z, s1.z, c1.z), 0.f);
                v1.w = fmaxf(fmaf(v1.w, s1.w, c1.w), 0.f);
            }
            pa0.x = f2tf(v0.x); pa0.y = f2tf(v0.y); pa0.z = f2tf(v0.z); pa0.w = f2tf(v0.w);
            pa1.x = f2tf(v1.x); pa1.y = f2tf(v1.y); pa1.z = f2tf(v1.z); pa1.w = f2tf(v1.w);
            float4 w0 = *(const float4*)(Wrow + k0);
            float4 w1 = *(const float4*)(Wrow + k0 + 4);
            float4 w2 = *(const float4*)(Wrow + k0 + 8);
            float4 w3 = *(const float4*)(Wrow + k0 + 12);
            pb0.x = f2tf(w0.x); pb0.y = f2tf(w0.y); pb0.z = f2tf(w0.z); pb0.w = f2tf(w0.w);
            pb1.x = f2tf(w1.x); pb1.y = f2tf(w1.y); pb1.z = f2tf(w1.z); pb1.w = f2tf(w1.w);
            pb2.x = f2tf(w2.x); pb2.y = f2tf(w2.y); pb2.z = f2tf(w2.z); pb2.w = f2tf(w2.w);
            pb3.x = f2tf(w3.x); pb3.y = f2tf(w3.y); pb3.z = f2tf(w3.z); pb3.w = f2tf(w3.w);
        }

        // compute on buffer b
        const float* Ab = Asm[b];
        const float* Bb = Bsm[b];
#pragma unroll
        for (int ks = 0; ks < 4; ks++) {
            const int kb = ks * 8;
            uint32_t af[4][4];
            uint32_t bf[4][2];
#pragma unroll
            for (int mt = 0; mt < 4; mt++) {
                const float* ap = Ab + (wm * 64 + mt * 16 + g) * SA + kb;
                af[mt][0] = __float_as_uint(ap[t]);
                af[mt][1] = __float_as_uint(ap[8 * SA + t]);
                af[mt][2] = __float_as_uint(ap[t + 4]);
                af[mt][3] = __float_as_uint(ap[8 * SA + t + 4]);
            }
#pragma unroll
            for (int nt = 0; nt < 4; nt++) {
                const float* bp = Bb + (wn * 32 + nt * 8 + g) * SB + kb;
                bf[nt][0] = __float_as_uint(bp[t]);
                bf[nt][1] = __float_as_uint(bp[t + 4]);
            }
#pragma unroll
            for (int mt = 0; mt < 4; mt++)
#pragma unroll
                for (int nt = 0; nt < 4; nt++)
                    mma_tf32(acc[mt][nt], af[mt][0], af[mt][1], af[mt][2], af[mt][3],
                             bf[nt][0], bf[nt][1]);
        }

        // store prefetched regs into the other buffer
        if (i + 1 < NCHUNK) {
            const int nb = (i + 1) & 1;
            float* ad = Asm[nb] + ar * SA + ak;
            *(float4*)ad = pa0;
            *(float4*)(ad + 4) = pa1;
            float* bd = Bsm[nb] + bn * SB + bk;
            *(float4*)bd = pb0;
            *(float4*)(bd + 4) = pb1;
            *(float4*)(bd + 8) = pb2;
            *(float4*)(bd + 12) = pb3;
            __syncthreads();
        }
    }

    // ---- epilogue: bias add, store, optional wout = C - sub ----
#pragma unroll
    for (int mt = 0; mt < 4; mt++) {
        const int r = row0 + wm * 64 + mt * 16 + g;
#pragma unroll
        for (int nt = 0; nt < 4; nt++) {
            const int c = wn * 32 + nt * 8 + 2 * t;
            const float2 bi = *(const float2*)(bias + c);
            float2 o0, o1;
            o0.x = acc[mt][nt][0] + bi.x;
            o0.y = acc[mt][nt][1] + bi.y;
            o1.x = acc[mt][nt][2] + bi.x;
            o1.y = acc[mt][nt][3] + bi.y;
            *(float2*)(C + (size_t)r * DD + c) = o0;
            *(float2*)(C + (size_t)(r + 8) * DD + c) = o1;
            if (wout != nullptr) {
                float2 s0 = *(const float2*)(sub + (size_t)r * DD + c);
                float2 s1 = *(const float2*)(sub + (size_t)(r + 8) * DD + c);
                float2 d0, d1;
                d0.x = o0.x - s0.x; d0.y = o0.y - s0.y;
                d1.x = o1.x - s1.x; d1.y = o1.y - s1.y;
                *(float2*)(wout + (size_t)r * DD + c) = d0;
                *(float2*)(wout + (size_t)(r + 8) * DD + c) = d1;
            }
        }
    }
}

// ---------------- BatchNorm stats ----------------
__global__ void zero_stats_k(float* stats) { stats[threadIdx.x] = 0.f; }

__global__ __launch_bounds__(256) void bn_reduce_k(const float* __restrict__ x,
                                                   float* __restrict__ stats)
{
    const int c = threadIdx.x;
    const int r0 = blockIdx.x * 128;
    float s = 0.f, q = 0.f;
    for (int r = r0; r < r0 + 128; r++) {
        float v = x[(size_t)r * DD + c];
        s += v;
        q = fmaf(v, v, q);
    }
    atomicAdd(&stats[c], s);
    atomicAdd(&stats[256 + c], q);
}

__global__ void bn_finalize_k(const float* __restrict__ stats,
                              const float* __restrict__ gamma,
                              const float* __restrict__ beta,
                              float* __restrict__ scale, float* __restrict__ shift)
{
    const int c = threadIdx.x;
    const float invM = 1.0f / (float)MM;
    float mean = stats[c] * invM;
    float var = stats[256 + c] * invM - mean * mean;
    float sc = gamma[c] * rsqrtf(var + EPSV);
    scale[c] = sc;
    shift[c] = beta[c] - mean * sc;
}

// ---------------- fused softmax(seq) * v sum ----------------
__global__ __launch_bounds__(256) void softmax_wv_k(const float* __restrict__ w,
                                                    const float* __restrict__ v,
                                                    float* __restrict__ xcat, int head)
{
    const int c = blockIdx.x * 32 + threadIdx.x;
    const int ty = threadIdx.y;
    float m = -1e30f, l = 0.f, a = 0.f;
    for (int s = ty; s < SS; s += 8) {
        const size_t idx = (size_t)s * (BB * DD) + c;
        float x = w[idx];
        float val = v[idx];
        float nm = fmaxf(m, x);
        float corr = __expf(m - nm);
        float e = __expf(x - nm);
        l = l * corr + e;
        a = a * corr + e * val;
        m = nm;
    }
    __shared__ float sm[8][32], sl[8][32], sa[8][32];
    sm[ty][threadIdx.x] = m;
    sl[ty][threadIdx.x] = l;
    sa[ty][threadIdx.x] = a;
    __syncthreads();
    if (ty == 0) {
        for (int j = 1; j < 8; j++) {
            float m2 = sm[j][threadIdx.x], l2 = sl[j][threadIdx.x], a2 = sa[j][threadIdx.x];
            float nm = fmaxf(m, m2);
            float c1 = __expf(m - nm), c2 = __expf(m2 - nm);
            l = l * c1 + l2 * c2;
            a = a * c1 + a2 * c2;
            m = nm;
        }
        int b = c >> 8, d = c & 255;
        xcat[b * (DD * HH) + head * DD + d] = a / l;
    }
}

// ---------------- tiny final MLP layer ----------------
__global__ __launch_bounds__(256) void mlp_k(const float* __restrict__ x,
                                             const float* __restrict__ Wt,
                                             const float* __restrict__ bias,
                                             float* __restrict__ y, int K, int do_relu)
{
    __shared__ float xs[1024];
    const int b = blockIdx.x;
    for (int i = threadIdx.x; i < K; i += 256) xs[i] = x[b * K + i];
    __syncthreads();
    const int n = threadIdx.x;
    float acc = bias[n];
    const float* wr = Wt + (size_t)n * K;
    for (int k = 0; k < K; k++) acc = fmaf(xs[k], wr[k], acc);
    if (do_relu) acc = fmaxf(acc, 0.f);
    y[b * DD + n] = acc;
}

// ---------------- driver ----------------
static float* sym(const void* s)
{
    void* p = nullptr;
    cudaGetSymbolAddress(&p, (const void*)s);
    return (float*)p;
}

extern "C" void kernel_launch(void* const* d_in, const int* in_sizes, int n_in,
                              void* d_out, int out_size)
{
    (void)in_sizes; (void)n_in; (void)out_size;
    const float* q_in = (const float*)d_in[0];
    const float* k_in = (const float*)d_in[1];
    const float* v_in = (const float*)d_in[2];
    const float* wq = (const float*)d_in[3];
    const float* bq = (const float*)d_in[4];
    const float* wk = (const float*)d_in[5];
    const float* bk = (const float*)d_in[6];
    const float* wv = (const float*)d_in[7];
    const float* bv = (const float*)d_in[8];
    const float* g1 = (const float*)d_in[9];
    const float* be1 = (const float*)d_in[10];
    const float* wl1 = (const float*)d_in[11];
    const float* bl1 = (const float*)d_in[12];
    const float* g2 = (const float*)d_in[13];
    const float* be2 = (const float*)d_in[14];
    const float* wl2 = (const float*)d_in[15];
    const float* bl2 = (const float*)d_in[16];
    const float* mw0 = (const float*)d_in[17];
    const float* mb0 = (const float*)d_in[18];
    const float* mw1 = (const float*)d_in[19];
    const float* mb1 = (const float*)d_in[20];
    const float* mw2 = (const float*)d_in[21];
    const float* mb2 = (const float*)d_in[22];

    float* qa = sym(g_qa); float* qb = sym(g_qb);
    float* ka = sym(g_ka); float* kb = sym(g_kb);
    float* va = sym(g_va); float* vb = sym(g_vb);
    float* w1 = sym(g_w1); float* w2 = sym(g_w2);
    float* stats = sym(g_stats);
    float* scale = sym(g_scale);
    float* shift = sym(g_shift);
    float* xcat = sym(g_xcat);
    float* m0 = sym(g_m0);
    float* m1 = sym(g_m1);

    cudaFuncSetAttribute(gemm_tc, cudaFuncAttributeMaxDynamicSharedMemorySize,
                         SMEM_BYTES);

    const int GG = MM / BLKM;   // 512 CTAs
    const float* qs = q_in; const float* ks = k_in; const float* vs = v_in;
    float* qpp[2] = { qa, qb };
    float* kpp[2] = { ka, kb };
    float* vpp[2] = { va, vb };

    for (int h = 0; h < HH; h++) {
        float* qd = qpp[h & 1];
        float* kd = kpp[h & 1];
        float* vd = vpp[h & 1];
        const float* Wq = wq + (size_t)h * DD * DD;
        const float* Wk = wk + (size_t)h * DD * DD;
        const float* Wv = wv + (size_t)h * DD * DD;

        gemm_tc<<<GG, 512, SMEM_BYTES>>>(qs, Wq, bq + h * DD, qd,
                                         nullptr, nullptr, nullptr, nullptr);
        gemm_tc<<<GG, 512, SMEM_BYTES>>>(vs, Wv, bv + h * DD, vd,
                                         nullptr, nullptr, nullptr, nullptr);
        // k projection with fused w1 = k_new - q_new
        gemm_tc<<<GG, 512, SMEM_BYTES>>>(ks, Wk, bk + h * DD, kd,
                                         nullptr, nullptr, qd, w1);

        zero_stats_k<<<1, 512>>>(stats);
        bn_reduce_k<<<MM / 128, 256>>>(w1, stats);
        bn_finalize_k<<<1, 256>>>(stats, g1 + h * DD, be1 + h * DD, scale, shift);
        gemm_tc<<<GG, 512, SMEM_BYTES>>>(w1, wl1 + (size_t)h * DD * DD, bl1 + h * DD,
                                         w2, scale, shift, nullptr, nullptr);

        zero_stats_k<<<1, 512>>>(stats);
        bn_reduce_k<<<MM / 128, 256>>>(w2, stats);
        bn_finalize_k<<<1, 256>>>(stats, g2 + h * DD, be2 + h * DD, scale, shift);
        gemm_tc<<<GG, 512, SMEM_BYTES>>>(w2, wl2 + (size_t)h * DD * DD, bl2 + h * DD,
                                         w1, scale, shift, nullptr, nullptr);

        softmax_wv_k<<<256, dim3(32, 8)>>>(w1, vd, xcat, h);

        qs = qd; ks = kd; vs = vd;
    }

    mlp_k<<<BB, 256>>>(xcat, mw0, mb0, m0, DD * HH, 1);
    mlp_k<<<BB, 256>>>(m0, mw1, mb1, m1, DD, 1);
    mlp_k<<<BB, 256>>>(m1, mw2, mb2, (float*)d_out, DD, 0);
}

// round 6
// speedup vs baseline: 2.2992x; 1.0776x over previous
#include <cuda_runtime.h>
#include <cstdint>
#include <cstddef>

// ---------------- problem constants ----------------
#define SS 2048
#define BB 32
#define DD 256
#define HH 4
#define MM (SS * BB)           // 65536 rows
#define SBD (SS * BB * DD)     // 16,777,216 elements
#define EPSV 1e-5f

// ---------------- GEMM config ----------------
#define BLKM 128               // rows per CTA
#define KCH 32                 // K per chunk
#define NCHUNK (DD / KCH)      // 8
#define SA 36                  // smem row stride (floats): bank = 4g+t bijective
#define A_FL (BLKM * SA)       // 4608 floats
#define B_FL (DD * SA)         // 9216 floats
#define STG_FL (A_FL + B_FL)   // 13824 floats per stage
#define NSTAGE 3
#define SMEM_BYTES (NSTAGE * STG_FL * 4)   // 165888 B

// ---------------- scratch (no cudaMalloc allowed) ----------------
__device__ float g_qa[SBD];
__device__ float g_qb[SBD];
__device__ float g_ka[SBD];
__device__ float g_kb[SBD];
__device__ float g_va[SBD];
__device__ float g_vb[SBD];
__device__ float g_w1[SBD];
__device__ float g_w2[SBD];
__device__ float g_stats8[8 * 512];      // per (head,stage) sum/sumsq
__device__ float g_scale[8 * 256];
__device__ float g_shift[8 * 256];
__device__ float g_xcat[BB * DD * HH];
__device__ float g_m0[BB * DD];
__device__ float g_m1[BB * DD];

// ---------------- helpers ----------------
__device__ __forceinline__ uint32_t smem_u32(const void* p)
{
    uint32_t a;
    asm("{ .reg .u64 t; cvta.to.shared.u64 t, %1; cvt.u32.u64 %0, t; }"
        : "=r"(a) : "l"(p));
    return a;
}

__device__ __forceinline__ uint32_t f2tf(float x)
{
    uint32_t r;
    asm("cvt.rna.tf32.f32 %0, %1;" : "=r"(r) : "f"(x));
    return r;
}

__device__ __forceinline__ void mma_tf32(float* d, uint32_t a0, uint32_t a1,
                                         uint32_t a2, uint32_t a3,
                                         uint32_t b0, uint32_t b1)
{
    asm volatile(
        "mma.sync.aligned.m16n8k8.row.col.f32.tf32.tf32.f32 "
        "{%0,%1,%2,%3}, {%4,%5,%6,%7}, {%8,%9}, {%0,%1,%2,%3};"
        : "+f"(d[0]), "+f"(d[1]), "+f"(d[2]), "+f"(d[3])
        : "r"(a0), "r"(a1), "r"(a2), "r"(a3), "r"(b0), "r"(b1));
}

__device__ __forceinline__ void cpa16(uint32_t dst, const void* src)
{
    asm volatile("cp.async.cg.shared.global [%0], [%1], 16;"
                 :: "r"(dst), "l"(src));
}
#define CP_COMMIT() asm volatile("cp.async.commit_group;" ::: "memory")
#define CP_WAIT1()  asm volatile("cp.async.wait_group 1;" ::: "memory")

// ---------------- GEMM: C[M,256] = act(A)[M,256] @ W[256,256]^T + bias ----------------
// BN: a' = relu(a*trs[k]+trb[k]) applied on fragment load.
// WOUT: wout = C - sub (and stats taken over wout). STATS: column sum/sumsq atomics.
template<bool BN, bool WOUT, bool STATS>
__global__ __launch_bounds__(512, 1) void gemm_tc(
    const float* __restrict__ A, const float* __restrict__ W,
    const float* __restrict__ bias, float* __restrict__ C,
    const float* __restrict__ trs, const float* __restrict__ trb,
    const float* __restrict__ sub, float* __restrict__ wout,
    float* __restrict__ stats)
{
    extern __shared__ float sm[];
    const uint32_t smb = smem_u32(sm);

    const int tid = threadIdx.x;
    const int wid = tid >> 5, lane = tid & 31;
    const int g = lane >> 2, t = lane & 3;
    const int wm = wid >> 3;        // 0..1 (64 rows)
    const int wn = wid & 7;         // 0..7 (32 cols)
    const int row0 = blockIdx.x * BLKM;

    // fill mapping
    const int ar = tid >> 2, ak = (tid & 3) * 8;
    const int bn_ = tid >> 1, bk = (tid & 1) * 16;
    const float* const aptr = A + (size_t)(row0 + ar) * DD + ak;
    const float* const wptr = W + (size_t)bn_ * DD + bk;
    const uint32_t a_soff = (uint32_t)(ar * SA + ak) * 4u;
    const uint32_t b_soff = (uint32_t)(A_FL + bn_ * SA + bk) * 4u;

    float acc[4][4][4];
#pragma unroll
    for (int mt = 0; mt < 4; mt++)
#pragma unroll
        for (int nt = 0; nt < 4; nt++)
#pragma unroll
            for (int j = 0; j < 4; j++) acc[mt][nt][j] = 0.f;

    // prologue: stage 0, 1 in flight
#pragma unroll
    for (int p = 0; p < 2; p++) {
        const uint32_t sb = smb + (uint32_t)(p * STG_FL) * 4u;
        const float* ap = aptr + p * KCH;
        cpa16(sb + a_soff, ap);
        cpa16(sb + a_soff + 16, ap + 4);
        const float* wp = wptr + p * KCH;
        const uint32_t bb = sb + b_soff;
        cpa16(bb, wp);
        cpa16(bb + 16, wp + 4);
        cpa16(bb + 32, wp + 8);
        cpa16(bb + 48, wp + 12);
        CP_COMMIT();
    }

#pragma unroll 1
    for (int i = 0; i < NCHUNK; i++) {
        CP_WAIT1();
        __syncthreads();

        // issue next stage
        if (i + 2 < NCHUNK) {
            const int s2 = (i + 2) % NSTAGE;
            const uint32_t sb = smb + (uint32_t)(s2 * STG_FL) * 4u;
            const float* ap = aptr + (i + 2) * KCH;
            cpa16(sb + a_soff, ap);
            cpa16(sb + a_soff + 16, ap + 4);
            const float* wp = wptr + (i + 2) * KCH;
            const uint32_t bb = sb + b_soff;
            cpa16(bb, wp);
            cpa16(bb + 16, wp + 4);
            cpa16(bb + 32, wp + 8);
            cpa16(bb + 48, wp + 12);
        }
        CP_COMMIT();

        const float* Ab = sm + (i % NSTAGE) * STG_FL;
        const float* Bb = Ab + A_FL;

        float s_lo[4], s_hi[4], c_lo[4], c_hi[4];
        if (BN) {
            const int k0 = i * KCH;
#pragma unroll
            for (int ks = 0; ks < 4; ks++) {
                s_lo[ks] = __ldg(trs + k0 + ks * 8 + t);
                s_hi[ks] = __ldg(trs + k0 + ks * 8 + 4 + t);
                c_lo[ks] = __ldg(trb + k0 + ks * 8 + t);
                c_hi[ks] = __ldg(trb + k0 + ks * 8 + 4 + t);
            }
        }

#pragma unroll
        for (int ks = 0; ks < 4; ks++) {
            uint32_t af[4][4], bf[4][2];
#pragma unroll
            for (int mt = 0; mt < 4; mt++) {
                const float* ap = Ab + (wm * 64 + mt * 16 + g) * SA + ks * 8;
                float v0 = ap[t];
                float v1 = ap[8 * SA + t];
                float v2 = ap[t + 4];
                float v3 = ap[8 * SA + t + 4];
                if (BN) {
                    v0 = fmaxf(fmaf(v0, s_lo[ks], c_lo[ks]), 0.f);
                    v1 = fmaxf(fmaf(v1, s_lo[ks], c_lo[ks]), 0.f);
                    v2 = fmaxf(fmaf(v2, s_hi[ks], c_hi[ks]), 0.f);
                    v3 = fmaxf(fmaf(v3, s_hi[ks], c_hi[ks]), 0.f);
                }
                af[mt][0] = f2tf(v0);
                af[mt][1] = f2tf(v1);
                af[mt][2] = f2tf(v2);
                af[mt][3] = f2tf(v3);
            }
#pragma unroll
            for (int nt = 0; nt < 4; nt++) {
                const float* bp = Bb + (wn * 32 + nt * 8 + g) * SA + ks * 8;
                bf[nt][0] = f2tf(bp[t]);
                bf[nt][1] = f2tf(bp[t + 4]);
            }
#pragma unroll
            for (int mt = 0; mt < 4; mt++)
#pragma unroll
                for (int nt = 0; nt < 4; nt++)
                    mma_tf32(acc[mt][nt], af[mt][0], af[mt][1], af[mt][2],
                             af[mt][3], bf[nt][0], bf[nt][1]);
        }
    }

    // ---- epilogue ----
    float csum[8], csq[8];
    if (STATS) {
#pragma unroll
        for (int j = 0; j < 8; j++) { csum[j] = 0.f; csq[j] = 0.f; }
    }

#pragma unroll
    for (int mt = 0; mt < 4; mt++) {
        const int r = row0 + wm * 64 + mt * 16 + g;
#pragma unroll
        for (int nt = 0; nt < 4; nt++) {
            const int c = wn * 32 + nt * 8 + 2 * t;
            const float2 bi = *(const float2*)(bias + c);
            float2 o0, o1;
            o0.x = acc[mt][nt][0] + bi.x;
            o0.y = acc[mt][nt][1] + bi.y;
            o1.x = acc[mt][nt][2] + bi.x;
            o1.y = acc[mt][nt][3] + bi.y;
            if (C != nullptr) {
                *(float2*)(C + (size_t)r * DD + c) = o0;
                *(float2*)(C + (size_t)(r + 8) * DD + c) = o1;
            }
            float2 v0 = o0, v1 = o1;
            if (WOUT) {
                float2 s0 = *(const float2*)(sub + (size_t)r * DD + c);
                float2 s1 = *(const float2*)(sub + (size_t)(r + 8) * DD + c);
                v0.x = o0.x - s0.x; v0.y = o0.y - s0.y;
                v1.x = o1.x - s1.x; v1.y = o1.y - s1.y;
                *(float2*)(wout + (size_t)r * DD + c) = v0;
                *(float2*)(wout + (size_t)(r + 8) * DD + c) = v1;
            }
            if (STATS) {
                csum[nt * 2 + 0] += v0.x + v1.x;
                csum[nt * 2 + 1] += v0.y + v1.y;
                csq[nt * 2 + 0] += v0.x * v0.x + v1.x * v1.x;
                csq[nt * 2 + 1] += v0.y * v0.y + v1.y * v1.y;
            }
        }
    }

    if (STATS) {
        // reduce over g (lane bits 2..4)
#pragma unroll
        for (int j = 0; j < 8; j++) {
#pragma unroll
            for (int off = 4; off < 32; off <<= 1) {
                csum[j] += __shfl_xor_sync(0xFFFFFFFFu, csum[j], off);
                csq[j] += __shfl_xor_sync(0xFFFFFFFFu, csq[j], off);
            }
        }
        if (g == 0) {
#pragma unroll
            for (int nt = 0; nt < 4; nt++) {
#pragma unroll
                for (int j = 0; j < 2; j++) {
                    const int c = wn * 32 + nt * 8 + 2 * t + j;
                    atomicAdd(&stats[c], csum[nt * 2 + j]);
                    atomicAdd(&stats[256 + c], csq[nt * 2 + j]);
                }
            }
        }
    }
}

// ---------------- zero all stats buffers (once per replay) ----------------
__global__ void zero_stats_k(float* stats)
{
    stats[blockIdx.x * 512 + threadIdx.x] = 0.f;
}

// ---------------- BN finalize: stats -> scale/shift ----------------
__global__ void bn_finalize_k(const float* __restrict__ stats,
                              const float* __restrict__ gamma,
                              const float* __restrict__ beta,
                              float* __restrict__ scale, float* __restrict__ shift)
{
    const int c = threadIdx.x;
    const float invM = 1.0f / (float)MM;
    float mean = stats[c] * invM;
    float var = stats[256 + c] * invM - mean * mean;
    float sc = gamma[c] * rsqrtf(var + EPSV);
    scale[c] = sc;
    shift[c] = beta[c] - mean * sc;
}

// ---------------- fused softmax(seq) * v sum ----------------
__global__ __launch_bounds__(256) void softmax_wv_k(const float* __restrict__ w,
                                                    const float* __restrict__ v,
                                                    float* __restrict__ xcat, int head)
{
    const int c = blockIdx.x * 32 + threadIdx.x;
    const int ty = threadIdx.y;
    float m = -1e30f, l = 0.f, a = 0.f;
    for (int s = ty; s < SS; s += 8) {
        const size_t idx = (size_t)s * (BB * DD) + c;
        float x = w[idx];
        float val = v[idx];
        float nm = fmaxf(m, x);
        float corr = __expf(m - nm);
        float e = __expf(x - nm);
        l = l * corr + e;
        a = a * corr + e * val;
        m = nm;
    }
    __shared__ float sm_[8][32], sl[8][32], sa[8][32];
    sm_[ty][threadIdx.x] = m;
    sl[ty][threadIdx.x] = l;
    sa[ty][threadIdx.x] = a;
    __syncthreads();
    if (ty == 0) {
        for (int j = 1; j < 8; j++) {
            float m2 = sm_[j][threadIdx.x], l2 = sl[j][threadIdx.x], a2 = sa[j][threadIdx.x];
            float nm = fmaxf(m, m2);
            float c1 = __expf(m - nm), c2 = __expf(m2 - nm);
            l = l * c1 + l2 * c2;
            a = a * c1 + a2 * c2;
            m = nm;
        }
        int b = c >> 8, d = c & 255;
        xcat[b * (DD * HH) + head * DD + d] = a / l;
    }
}

// ---------------- tiny final MLP layer ----------------
__global__ __launch_bounds__(256) void mlp_k(const float* __restrict__ x,
                                             const float* __restrict__ Wt,
                                             const float* __restrict__ bias,
                                             float* __restrict__ y, int K, int do_relu)
{
    __shared__ float xs[1024];
    const int b = blockIdx.x;
    for (int i = threadIdx.x; i < K; i += 256) xs[i] = x[b * K + i];
    __syncthreads();
    const int n = threadIdx.x;
    float acc = bias[n];
    const float* wr = Wt + (size_t)n * K;
    for (int k = 0; k < K; k++) acc = fmaf(xs[k], wr[k], acc);
    if (do_relu) acc = fmaxf(acc, 0.f);
    y[b * DD + n] = acc;
}

// ---------------- driver ----------------
static float* sym(const void* s)
{
    void* p = nullptr;
    cudaGetSymbolAddress(&p, (const void*)s);
    return (float*)p;
}

extern "C" void kernel_launch(void* const* d_in, const int* in_sizes, int n_in,
                              void* d_out, int out_size)
{
    (void)in_sizes; (void)n_in; (void)out_size;
    const float* q_in = (const float*)d_in[0];
    const float* k_in = (const float*)d_in[1];
    const float* v_in = (const float*)d_in[2];
    const float* wq = (const float*)d_in[3];
    const float* bq = (const float*)d_in[4];
    const float* wk = (const float*)d_in[5];
    const float* bk = (const float*)d_in[6];
    const float* wv = (const float*)d_in[7];
    const float* bv = (const float*)d_in[8];
    const float* g1 = (const float*)d_in[9];
    const float* be1 = (const float*)d_in[10];
    const float* wl1 = (const float*)d_in[11];
    const float* bl1 = (const float*)d_in[12];
    const float* g2 = (const float*)d_in[13];
    const float* be2 = (const float*)d_in[14];
    const float* wl2 = (const float*)d_in[15];
    const float* bl2 = (const float*)d_in[16];
    const float* mw0 = (const float*)d_in[17];
    const float* mb0 = (const float*)d_in[18];
    const float* mw1 = (const float*)d_in[19];
    const float* mb1 = (const float*)d_in[20];
    const float* mw2 = (const float*)d_in[21];
    const float* mb2 = (const float*)d_in[22];

    float* qa = sym(g_qa); float* qb = sym(g_qb);
    float* ka = sym(g_ka); float* kb = sym(g_kb);
    float* va = sym(g_va); float* vb = sym(g_vb);
    float* w1 = sym(g_w1); float* w2 = sym(g_w2);
    float* stats8 = sym(g_stats8);
    float* scale8 = sym(g_scale);
    float* shift8 = sym(g_shift);
    float* xcat = sym(g_xcat);
    float* m0 = sym(g_m0);
    float* m1 = sym(g_m1);

    cudaFuncSetAttribute(gemm_tc<false, false, false>,
                         cudaFuncAttributeMaxDynamicSharedMemorySize, SMEM_BYTES);
    cudaFuncSetAttribute(gemm_tc<false, true, true>,
                         cudaFuncAttributeMaxDynamicSharedMemorySize, SMEM_BYTES);
    cudaFuncSetAttribute(gemm_tc<true, false, true>,
                         cudaFuncAttributeMaxDynamicSharedMemorySize, SMEM_BYTES);
    cudaFuncSetAttribute(gemm_tc<true, false, false>,
                         cudaFuncAttributeMaxDynamicSharedMemorySize, SMEM_BYTES);

    const int GG = MM / BLKM;   // 512 CTAs

    zero_stats_k<<<8, 512>>>(stats8);

    const float* qs = q_in; const float* ks = k_in; const float* vs = v_in;
    float* qpp[2] = { qa, qb };
    float* kpp[2] = { ka, kb };
    float* vpp[2] = { va, vb };

    for (int h = 0; h < HH; h++) {
        float* qd = qpp[h & 1];
        float* kd = kpp[h & 1];
        float* vd = vpp[h & 1];
        const float* Wq = wq + (size_t)h * DD * DD;
        const float* Wk = wk + (size_t)h * DD * DD;
        const float* Wv = wv + (size_t)h * DD * DD;
        float* st1 = stats8 + (size_t)(2 * h) * 512;
        float* st2 = stats8 + (size_t)(2 * h + 1) * 512;
        float* sc1 = scale8 + (size_t)(2 * h) * 256;
        float* sh1 = shift8 + (size_t)(2 * h) * 256;
        float* sc2 = scale8 + (size_t)(2 * h + 1) * 256;
        float* sh2 = shift8 + (size_t)(2 * h + 1) * 256;

        gemm_tc<false, false, false><<<GG, 512, SMEM_BYTES>>>(
            qs, Wq, bq + h * DD, qd, nullptr, nullptr, nullptr, nullptr, nullptr);
        gemm_tc<false, false, false><<<GG, 512, SMEM_BYTES>>>(
            vs, Wv, bv + h * DD, vd, nullptr, nullptr, nullptr, nullptr, nullptr);
        // k projection: kd (skipped on last head), w1 = kd - qd, BN1 stats
        gemm_tc<false, true, true><<<GG, 512, SMEM_BYTES>>>(
            ks, Wk, bk + h * DD, (h == HH - 1) ? nullptr : kd,
            nullptr, nullptr, qd, w1, st1);

        bn_finalize_k<<<1, 256>>>(st1, g1 + h * DD, be1 + h * DD, sc1, sh1);
        // w2 = relu(bn1(w1)) @ wl1^T + bl1, BN2 stats fused
        gemm_tc<true, false, true><<<GG, 512, SMEM_BYTES>>>(
            w1, wl1 + (size_t)h * DD * DD, bl1 + h * DD, w2,
            sc1, sh1, nullptr, nullptr, st2);

        bn_finalize_k<<<1, 256>>>(st2, g2 + h * DD, be2 + h * DD, sc2, sh2);
        // w1 = relu(bn2(w2)) @ wl2^T + bl2
        gemm_tc<true, false, false><<<GG, 512, SMEM_BYTES>>>(
            w2, wl2 + (size_t)h * DD * DD, bl2 + h * DD, w1,
            sc2, sh2, nullptr, nullptr, nullptr);

        softmax_wv_k<<<256, dim3(32, 8)>>>(w1, vd, xcat, h);

        qs = qd; ks = kd; vs = vd;
    }

    mlp_k<<<BB, 256>>>(xcat, mw0, mb0, m0, DD * HH, 1);
    mlp_k<<<BB, 256>>>(m0, mw1, mb1, m1, DD, 1);
    mlp_k<<<BB, 256>>>(m1, mw2, mb2, (float*)d_out, DD, 0);
}

// round 10
// speedup vs baseline: 2.5354x; 1.1027x over previous
#include <cuda_runtime.h>
#include <cstdint>
#include <cstddef>

// ---------------- problem constants ----------------
#define SS 2048
#define BB 32
#define DD 256
#define HH 4
#define MM (SS * BB)           // 65536 rows
#define SBD (SS * BB * DD)     // 16,777,216 elements
#define EPSV 1e-5f

// ---------------- GEMM config ----------------
#define BLKM 128
#define BLKN 128
#define KCH 32
#define NCHUNK (DD / KCH)      // 8
#define SA 40                  // smem row stride (floats); LDS.64 conflict-free
#define A_FL (BLKM * SA)       // 5120 floats
#define STG_FL (2 * A_FL)      // A + B per stage
#define NSTAGE 2
#define SMEM_BYTES (NSTAGE * STG_FL * 4)   // 81920 B

// ---------------- scratch (no cudaMalloc allowed) ----------------
__device__ float g_qa[SBD];
__device__ float g_qb[SBD];
__device__ float g_ka[SBD];
__device__ float g_kb[SBD];
__device__ float g_va[SBD];
__device__ float g_vb[SBD];
__device__ float g_w1[SBD];
__device__ float g_w2[SBD];
__device__ float g_wp[20 * DD * DD];     // preconverted tf32 (permuted) weights
__device__ float g_biasp[20 * DD];       // permuted biases
__device__ float g_stats8[8 * 512];
__device__ float g_scale[8 * 256];
__device__ float g_shift[8 * 256];
__device__ float g_xcat[BB * DD * HH];
__device__ float g_m0[BB * DD];
__device__ float g_m1[BB * DD];

// ---------------- helpers ----------------
__device__ __forceinline__ uint32_t smem_u32(const void* p)
{
    uint32_t a;
    asm("{ .reg .u64 t; cvta.to.shared.u64 t, %1; cvt.u32.u64 %0, t; }"
        : "=r"(a) : "l"(p));
    return a;
}

__device__ __forceinline__ uint32_t f2tf(float x)
{
    uint32_t r;
    asm("cvt.rna.tf32.f32 %0, %1;" : "=r"(r) : "f"(x));
    return r;
}

// permutation within each 8-block: natural k -> stored position
__device__ __forceinline__ int permc(int i)
{
    int i8 = i & 7;
    int pp = (i8 < 4) ? (2 * i8) : (2 * (i8 - 4) + 1);
    return (i & ~7) | pp;
}
// stored position -> natural k
__device__ __forceinline__ int unpermc(int p)
{
    int i8 = p & 7;
    int nat = (i8 >> 1) + ((i8 & 1) ? 4 : 0);
    return (p & ~7) | nat;
}

__device__ __forceinline__ void mma_tf32(float* d, uint32_t a0, uint32_t a1,
                                         uint32_t a2, uint32_t a3,
                                         uint32_t b0, uint32_t b1)
{
    asm volatile(
        "mma.sync.aligned.m16n8k8.row.col.f32.tf32.tf32.f32 "
        "{%0,%1,%2,%3}, {%4,%5,%6,%7}, {%8,%9}, {%0,%1,%2,%3};"
        : "+f"(d[0]), "+f"(d[1]), "+f"(d[2]), "+f"(d[3])
        : "r"(a0), "r"(a1), "r"(a2), "r"(a3), "r"(b0), "r"(b1));
}

__device__ __forceinline__ void cpa16(uint32_t dst, const void* src)
{
    asm volatile("cp.async.cg.shared.global [%0], [%1], 16;"
                 :: "r"(dst), "l"(src));
}
#define CP_COMMIT() asm volatile("cp.async.commit_group;" ::: "memory")
#define CP_WAIT1()  asm volatile("cp.async.wait_group 1;" ::: "memory")

// ---------------- weight preprocessing: tf32 + permute ----------------
// m = blockIdx.y in 0..19 -> head h = m/5, sel = m%5 {q,k,v,l1,l2}
// rows always permuted (output channels). cols permuted whenever the GEMM's
// input is in permuted space: everything except h==0 q/k/v projections.
__global__ void prep_w(const float* __restrict__ wq, const float* __restrict__ wk,
                       const float* __restrict__ wv, const float* __restrict__ wl1,
                       const float* __restrict__ wl2,
                       const float* __restrict__ bq, const float* __restrict__ bk,
                       const float* __restrict__ bv, const float* __restrict__ bl1,
                       const float* __restrict__ bl2,
                       float* __restrict__ wp, float* __restrict__ biasp)
{
    const int m = blockIdx.y;
    const int row = blockIdx.x;
    const int col = threadIdx.x;
    const int h = m / 5, sel = m % 5;
    const float* W; const float* B;
    switch (sel) {
        case 0: W = wq; B = bq; break;
        case 1: W = wk; B = bk; break;
        case 2: W = wv; B = bv; break;
        case 3: W = wl1; B = bl1; break;
        default: W = wl2; B = bl2; break;
    }
    const float v = W[(size_t)h * DD * DD + (size_t)row * DD + col];
    const int prow = permc(row);
    const int pcol = (h > 0 || sel >= 3) ? permc(col) : col;   // FIX: l1/l2 inputs
    wp[(size_t)m * DD * DD + (size_t)prow * DD + pcol] = __uint_as_float(f2tf(v));
    if (row == 0)
        biasp[m * DD + permc(col)] = B[h * DD + col];
}

// ---------------- GEMM ----------------
// C[M,256] = act(A)[M,256] @ Wp^T + biasp   (output in permuted channel space)
// KPERM: A smem k-order is permuted (pairs adjacent, LDS.64). BN: relu(a*s+c) on load.
// WOUT: wout = C - sub; STATS: column sum/sumsq atomics over (WOUT? wout : C).
template<bool KPERM, bool BN, bool WOUT, bool STATS>
__global__ __launch_bounds__(256, 2) void gemm_tc(
    const float* __restrict__ A, const float* __restrict__ Wp,
    const float* __restrict__ bias, float* __restrict__ C,
    const float* __restrict__ trs, const float* __restrict__ trb,
    const float* __restrict__ sub, float* __restrict__ wout,
    float* __restrict__ stats)
{
    extern __shared__ float sm[];
    const uint32_t smb = smem_u32(sm);

    const int tid = threadIdx.x;
    const int wid = tid >> 5, lane = tid & 31;
    const int g = lane >> 2, t = lane & 3;
    const int wm = wid >> 2;        // 0..1 (64 rows)
    const int wn = wid & 3;         // 0..3 (32 cols)
    const int row0 = blockIdx.y * BLKM;
    const int col0 = blockIdx.x * BLKN;

    // fill mapping: thread -> one half-row of 16 floats
    const int fr = tid >> 1, fk = (tid & 1) * 16;
    const float* const aptr = A + (size_t)(row0 + fr) * DD + fk;
    const float* const wptr = Wp + (size_t)(col0 + fr) * DD + fk;
    const uint32_t a_soff = (uint32_t)(fr * SA + fk) * 4u;
    const uint32_t b_soff = (uint32_t)(A_FL + fr * SA + fk) * 4u;

    float acc[4][4][4];
#pragma unroll
    for (int mt = 0; mt < 4; mt++)
#pragma unroll
        for (int nt = 0; nt < 4; nt++)
#pragma unroll
            for (int j = 0; j < 4; j++) acc[mt][nt][j] = 0.f;

    // prologue: stage 0
    {
        const uint32_t sb = smb;
#pragma unroll
        for (int j = 0; j < 4; j++) cpa16(sb + a_soff + j * 16, aptr + j * 4);
#pragma unroll
        for (int j = 0; j < 4; j++) cpa16(sb + b_soff + j * 16, wptr + j * 4);
        CP_COMMIT();
    }

#pragma unroll 1
    for (int i = 0; i < NCHUNK; i++) {
        if (i + 1 < NCHUNK) {
            const uint32_t sb = smb + (uint32_t)(((i + 1) & 1) * STG_FL) * 4u;
            const float* ap = aptr + (i + 1) * KCH;
            const float* wp2 = wptr + (i + 1) * KCH;
#pragma unroll
            for (int j = 0; j < 4; j++) cpa16(sb + a_soff + j * 16, ap + j * 4);
#pragma unroll
            for (int j = 0; j < 4; j++) cpa16(sb + b_soff + j * 16, wp2 + j * 4);
        }
        CP_COMMIT();
        CP_WAIT1();
        __syncthreads();

        const float* Ab = sm + (i & 1) * STG_FL;
        const float* Bb = Ab + A_FL;

#pragma unroll
        for (int ks = 0; ks < 4; ks++) {
            float2 sv, cv;
            if (BN) {
                sv = *(const float2*)(trs + i * KCH + ks * 8 + 2 * t);
                cv = *(const float2*)(trb + i * KCH + ks * 8 + 2 * t);
            }
            uint32_t af[4][4], bf[4][2];
#pragma unroll
            for (int mt = 0; mt < 4; mt++) {
                const float* ap = Ab + (wm * 64 + mt * 16 + g) * SA + ks * 8;
                float v0, v1, v2, v3;
                if (KPERM) {
                    float2 p0 = *(const float2*)(ap + 2 * t);
                    float2 p1 = *(const float2*)(ap + 8 * SA + 2 * t);
                    v0 = p0.x; v2 = p0.y; v1 = p1.x; v3 = p1.y;
                } else {
                    v0 = ap[t]; v1 = ap[8 * SA + t];
                    v2 = ap[t + 4]; v3 = ap[8 * SA + t + 4];
                }
                if (BN) {
                    v0 = fmaxf(fmaf(v0, sv.x, cv.x), 0.f);
                    v1 = fmaxf(fmaf(v1, sv.x, cv.x), 0.f);
                    v2 = fmaxf(fmaf(v2, sv.y, cv.y), 0.f);
                    v3 = fmaxf(fmaf(v3, sv.y, cv.y), 0.f);
                }
                af[mt][0] = f2tf(v0);
                af[mt][1] = f2tf(v1);
                af[mt][2] = f2tf(v2);
                af[mt][3] = f2tf(v3);
            }
#pragma unroll
            for (int nt = 0; nt < 4; nt++) {
                const float* bp = Bb + (wn * 32 + nt * 8 + g) * SA + ks * 8;
                if (KPERM) {
                    float2 p = *(const float2*)(bp + 2 * t);
                    bf[nt][0] = __float_as_uint(p.x);
                    bf[nt][1] = __float_as_uint(p.y);
                } else {
                    bf[nt][0] = __float_as_uint(bp[t]);
                    bf[nt][1] = __float_as_uint(bp[t + 4]);
                }
            }
#pragma unroll
            for (int mt = 0; mt < 4; mt++)
#pragma unroll
                for (int nt = 0; nt < 4; nt++)
                    mma_tf32(acc[mt][nt], af[mt][0], af[mt][1], af[mt][2],
                             af[mt][3], bf[nt][0], bf[nt][1]);
        }
        if (i + 1 < NCHUNK) __syncthreads();
    }

    // ---- epilogue ----
    float csum[8], csq[8];
    if (STATS) {
#pragma unroll
        for (int j = 0; j < 8; j++) { csum[j] = 0.f; csq[j] = 0.f; }
    }

#pragma unroll
    for (int mt = 0; mt < 4; mt++) {
        const int r = row0 + wm * 64 + mt * 16 + g;
#pragma unroll
        for (int nt = 0; nt < 4; nt++) {
            const int c = col0 + wn * 32 + nt * 8 + 2 * t;
            const float2 bi = *(const float2*)(bias + c);
            float2 o0, o1;
            o0.x = acc[mt][nt][0] + bi.x;
            o0.y = acc[mt][nt][1] + bi.y;
            o1.x = acc[mt][nt][2] + bi.x;
            o1.y = acc[mt][nt][3] + bi.y;
            if (C != nullptr) {
                *(float2*)(C + (size_t)r * DD + c) = o0;
                *(float2*)(C + (size_t)(r + 8) * DD + c) = o1;
            }
            float2 v0 = o0, v1 = o1;
            if (WOUT) {
                float2 s0 = *(const float2*)(sub + (size_t)r * DD + c);
                float2 s1 = *(const float2*)(sub + (size_t)(r + 8) * DD + c);
                v0.x = o0.x - s0.x; v0.y = o0.y - s0.y;
                v1.x = o1.x - s1.x; v1.y = o1.y - s1.y;
                *(float2*)(wout + (size_t)r * DD + c) = v0;
                *(float2*)(wout + (size_t)(r + 8) * DD + c) = v1;
            }
            if (STATS) {
                csum[nt * 2 + 0] += v0.x + v1.x;
                csum[nt * 2 + 1] += v0.y + v1.y;
                csq[nt * 2 + 0] += v0.x * v0.x + v1.x * v1.x;
                csq[nt * 2 + 1] += v0.y * v0.y + v1.y * v1.y;
            }
        }
    }

    if (STATS) {
#pragma unroll
        for (int j = 0; j < 8; j++) {
#pragma unroll
            for (int off = 4; off < 32; off <<= 1) {
                csum[j] += __shfl_xor_sync(0xFFFFFFFFu, csum[j], off);
                csq[j] += __shfl_xor_sync(0xFFFFFFFFu, csq[j], off);
            }
        }
        if (g == 0) {
#pragma unroll
            for (int nt = 0; nt < 4; nt++) {
#pragma unroll
                for (int j = 0; j < 2; j++) {
                    const int c = col0 + wn * 32 + nt * 8 + 2 * t + j;
                    atomicAdd(&stats[c], csum[nt * 2 + j]);
                    atomicAdd(&stats[256 + c], csq[nt * 2 + j]);
                }
            }
        }
    }
}

// ---------------- zero stats ----------------
__global__ void zero_stats_k(float* stats)
{
    stats[blockIdx.x * 512 + threadIdx.x] = 0.f;
}

// ---------------- BN finalize (permuted space) ----------------
__global__ void bn_finalize_k(const float* __restrict__ stats,
                              const float* __restrict__ gamma,
                              const float* __restrict__ beta,
                              float* __restrict__ scale, float* __restrict__ shift)
{
    const int p = threadIdx.x;
    const int c = unpermc(p);
    const float invM = 1.0f / (float)MM;
    float mean = stats[p] * invM;
    float var = stats[256 + p] * invM - mean * mean;
    float sc = gamma[c] * rsqrtf(var + EPSV);
    scale[p] = sc;
    shift[p] = beta[c] - mean * sc;
}

// ---------------- fused softmax(seq) * v sum (permuted in, natural out) ----------------
__global__ __launch_bounds__(256) void softmax_wv_k(const float* __restrict__ w,
                                                    const float* __restrict__ v,
                                                    float* __restrict__ xcat, int head)
{
    const int c = blockIdx.x * 32 + threadIdx.x;   // permuted-space column
    const int ty = threadIdx.y;
    float m = -1e30f, l = 0.f, a = 0.f;
    for (int s = ty; s < SS; s += 8) {
        const size_t idx = (size_t)s * (BB * DD) + c;
        float x = w[idx];
        float val = v[idx];
        float nm = fmaxf(m, x);
        float corr = __expf(m - nm);
        float e = __expf(x - nm);
        l = l * corr + e;
        a = a * corr + e * val;
        m = nm;
    }
    __shared__ float sm_[8][32], sl[8][32], sa[8][32];
    sm_[ty][threadIdx.x] = m;
    sl[ty][threadIdx.x] = l;
    sa[ty][threadIdx.x] = a;
    __syncthreads();
    if (ty == 0) {
        for (int j = 1; j < 8; j++) {
            float m2 = sm_[j][threadIdx.x], l2 = sl[j][threadIdx.x], a2 = sa[j][threadIdx.x];
            float nm = fmaxf(m, m2);
            float c1 = __expf(m - nm), c2 = __expf(m2 - nm);
            l = l * c1 + l2 * c2;
            a = a * c1 + a2 * c2;
            m = nm;
        }
        const int b = c >> 8;
        const int d = unpermc(c & 255);   // back to natural channel
        xcat[b * (DD * HH) + head * DD + d] = a / l;
    }
}

// ---------------- tiny final MLP layer ----------------
__global__ __launch_bounds__(256) void mlp_k(const float* __restrict__ x,
                                             const float* __restrict__ Wt,
                                             const float* __restrict__ bias,
                                             float* __restrict__ y, int K, int do_relu)
{
    __shared__ float xs[1024];
    const int b = blockIdx.x;
    for (int i = threadIdx.x; i < K; i += 256) xs[i] = x[b * K + i];
    __syncthreads();
    const int n = threadIdx.x;
    float acc = bias[n];
    const float* wr = Wt + (size_t)n * K;
    for (int k = 0; k < K; k++) acc = fmaf(xs[k], wr[k], acc);
    if (do_relu) acc = fmaxf(acc, 0.f);
    y[b * DD + n] = acc;
}

// ---------------- driver ----------------
static float* sym(const void* s)
{
    void* p = nullptr;
    cudaGetSymbolAddress(&p, (const void*)s);
    return (float*)p;
}

extern "C" void kernel_launch(void* const* d_in, const int* in_sizes, int n_in,
                              void* d_out, int out_size)
{
    (void)in_sizes; (void)n_in; (void)out_size;
    const float* q_in = (const float*)d_in[0];
    const float* k_in = (const float*)d_in[1];
    const float* v_in = (const float*)d_in[2];
    const float* wq = (const float*)d_in[3];
    const float* bq = (const float*)d_in[4];
    const float* wk = (const float*)d_in[5];
    const float* bk = (const float*)d_in[6];
    const float* wv = (const float*)d_in[7];
    const float* bv = (const float*)d_in[8];
    const float* g1 = (const float*)d_in[9];
    const float* be1 = (const float*)d_in[10];
    const float* wl1 = (const float*)d_in[11];
    const float* bl1 = (const float*)d_in[12];
    const float* g2 = (const float*)d_in[13];
    const float* be2 = (const float*)d_in[14];
    const float* wl2 = (const float*)d_in[15];
    const float* bl2 = (const float*)d_in[16];
    const float* mw0 = (const float*)d_in[17];
    const float* mb0 = (const float*)d_in[18];
    const float* mw1 = (const float*)d_in[19];
    const float* mb1 = (const float*)d_in[20];
    const float* mw2 = (const float*)d_in[21];
    const float* mb2 = (const float*)d_in[22];

    float* qa = sym(g_qa); float* qb = sym(g_qb);
    float* ka = sym(g_ka); float* kb = sym(g_kb);
    float* va = sym(g_va); float* vb = sym(g_vb);
    float* w1 = sym(g_w1); float* w2 = sym(g_w2);
    float* wp = sym(g_wp);
    float* biasp = sym(g_biasp);
    float* stats8 = sym(g_stats8);
    float* scale8 = sym(g_scale);
    float* shift8 = sym(g_shift);
    float* xcat = sym(g_xcat);
    float* m0 = sym(g_m0);
    float* m1 = sym(g_m1);

    cudaFuncSetAttribute(gemm_tc<false, false, false, false>,
                         cudaFuncAttributeMaxDynamicSharedMemorySize, SMEM_BYTES);
    cudaFuncSetAttribute(gemm_tc<false, false, true, true>,
                         cudaFuncAttributeMaxDynamicSharedMemorySize, SMEM_BYTES);
    cudaFuncSetAttribute(gemm_tc<true, false, false, false>,
                         cudaFuncAttributeMaxDynamicSharedMemorySize, SMEM_BYTES);
    cudaFuncSetAttribute(gemm_tc<true, false, true, true>,
                         cudaFuncAttributeMaxDynamicSharedMemorySize, SMEM_BYTES);
    cudaFuncSetAttribute(gemm_tc<true, true, false, true>,
                         cudaFuncAttributeMaxDynamicSharedMemorySize, SMEM_BYTES);
    cudaFuncSetAttribute(gemm_tc<true, true, false, false>,
                         cudaFuncAttributeMaxDynamicSharedMemorySize, SMEM_BYTES);

    // preprocess weights + biases (tf32, permuted) and zero stats
    prep_w<<<dim3(DD, 20), DD>>>(wq, wk, wv, wl1, wl2, bq, bk, bv, bl1, bl2,
                                 wp, biasp);
    zero_stats_k<<<8, 512>>>(stats8);

    const dim3 gg(DD / BLKN, MM / BLKM);   // (2, 512)
    const float* qs = q_in; const float* ks = k_in; const float* vs = v_in;
    float* qpp[2] = { qa, qb };
    float* kpp[2] = { ka, kb };
    float* vpp[2] = { va, vb };

    for (int h = 0; h < HH; h++) {
        float* qd = qpp[h & 1];
        float* kd = kpp[h & 1];
        float* vd = vpp[h & 1];
        const int mq = h * 5 + 0, mk = h * 5 + 1, mv = h * 5 + 2;
        const int ml1 = h * 5 + 3, ml2 = h * 5 + 4;
        const float* Wq = wp + (size_t)mq * DD * DD;
        const float* Wk = wp + (size_t)mk * DD * DD;
        const float* Wv = wp + (size_t)mv * DD * DD;
        const float* Wm1 = wp + (size_t)ml1 * DD * DD;
        const float* Wm2 = wp + (size_t)ml2 * DD * DD;
        float* st1 = stats8 + (size_t)(2 * h) * 512;
        float* st2 = stats8 + (size_t)(2 * h + 1) * 512;
        float* sc1 = scale8 + (size_t)(2 * h) * 256;
        float* sh1 = shift8 + (size_t)(2 * h) * 256;
        float* sc2 = scale8 + (size_t)(2 * h + 1) * 256;
        float* sh2 = shift8 + (size_t)(2 * h + 1) * 256;

        if (h == 0) {
            gemm_tc<false, false, false, false><<<gg, 256, SMEM_BYTES>>>(
                qs, Wq, biasp + mq * DD, qd, nullptr, nullptr, nullptr, nullptr,
                nullptr);
            gemm_tc<false, false, false, false><<<gg, 256, SMEM_BYTES>>>(
                vs, Wv, biasp + mv * DD, vd, nullptr, nullptr, nullptr, nullptr,
                nullptr);
            gemm_tc<false, false, true, true><<<gg, 256, SMEM_BYTES>>>(
                ks, Wk, biasp + mk * DD, kd, nullptr, nullptr, qd, w1, st1);
        } else {
            gemm_tc<true, false, false, false><<<gg, 256, SMEM_BYTES>>>(
                qs, Wq, biasp + mq * DD, qd, nullptr, nullptr, nullptr, nullptr,
                nullptr);
            gemm_tc<true, false, false, false><<<gg, 256, SMEM_BYTES>>>(
                vs, Wv, biasp + mv * DD, vd, nullptr, nullptr, nullptr, nullptr,
                nullptr);
            gemm_tc<true, false, true, true><<<gg, 256, SMEM_BYTES>>>(
                ks, Wk, biasp + mk * DD, (h == HH - 1) ? nullptr : kd,
                nullptr, nullptr, qd, w1, st1);
        }

        bn_finalize_k<<<1, 256>>>(st1, g1 + h * DD, be1 + h * DD, sc1, sh1);
        gemm_tc<true, true, false, true><<<gg, 256, SMEM_BYTES>>>(
            w1, Wm1, biasp + ml1 * DD, w2, sc1, sh1, nullptr, nullptr, st2);

        bn_finalize_k<<<1, 256>>>(st2, g2 + h * DD, be2 + h * DD, sc2, sh2);
        gemm_tc<true, true, false, false><<<gg, 256, SMEM_BYTES>>>(
            w2, Wm2, biasp + ml2 * DD, w1, sc2, sh2, nullptr, nullptr, nullptr);

        softmax_wv_k<<<256, dim3(32, 8)>>>(w1, vd, xcat, h);

        qs = qd; ks = kd; vs = vd;
    }

    mlp_k<<<BB, 256>>>(xcat, mw0, mb0, m0, DD * HH, 1);
    mlp_k<<<BB, 256>>>(m0, mw1, mb1, m1, DD, 1);
    mlp_k<<<BB, 256>>>(m1, mw2, mb2, (float*)d_out, DD, 0);
}

// round 11
// speedup vs baseline: 2.5517x; 1.0064x over previous
#include <cuda_runtime.h>
#include <cstdint>
#include <cstddef>

// ---------------- problem constants ----------------
#define SS 2048
#define BB 32
#define DD 256
#define HH 4
#define MM (SS * BB)           // 65536 rows
#define SBD (SS * BB * DD)     // 16,777,216 elements
#define EPSV 1e-5f

// ---------------- GEMM config ----------------
#define BLKM 128
#define BLKN 128
#define KCH 32
#define NCHUNK (DD / KCH)      // 8
#define SA 36                  // smem row stride (floats); LDS.128 conflict-free
#define A_FL (BLKM * SA)       // 4608 floats
#define STG_FL (2 * A_FL)      // A + B per stage (9216 floats = 36 KB)
#define NSTAGE 3
#define SMEM_BYTES (NSTAGE * STG_FL * 4)   // 110592 B

// ---------------- scratch (no cudaMalloc allowed) ----------------
__device__ float g_qa[SBD];
__device__ float g_qb[SBD];
__device__ float g_ka[SBD];
__device__ float g_kb[SBD];
__device__ float g_va[SBD];
__device__ float g_vb[SBD];
__device__ float g_w1[SBD];
__device__ float g_w2[SBD];
__device__ float g_wp[20 * DD * DD];     // preconverted tf32 (permuted) weights
__device__ float g_biasp[20 * DD];       // permuted biases
__device__ float g_stats8[8 * 512];
__device__ float g_scale[8 * 256];
__device__ float g_shift[8 * 256];
__device__ float g_xcat[BB * DD * HH];
__device__ float g_m0[BB * DD];
__device__ float g_m1[BB * DD];

// ---------------- helpers ----------------
__device__ __forceinline__ uint32_t smem_u32(const void* p)
{
    uint32_t a;
    asm("{ .reg .u64 t; cvta.to.shared.u64 t, %1; cvt.u32.u64 %0, t; }"
        : "=r"(a) : "l"(p));
    return a;
}

__device__ __forceinline__ uint32_t f2tf(float x)
{
    uint32_t r;
    asm("cvt.rna.tf32.f32 %0, %1;" : "=r"(r) : "f"(x));
    return r;
}
__device__ __forceinline__ float f2tff(float x)
{
    return __uint_as_float(f2tf(x));
}

// full 32-wide permutation: natural k -> stored pos = 8t + 2ks + half
// (k = ks*8 + half*4 + t within each 32-block)
__device__ __forceinline__ int permc32(int k)
{
    int k5 = k & 31;
    int t = k5 & 3, half = (k5 >> 2) & 1, ks = k5 >> 3;
    return (k & ~31) | (t * 8 + ks * 2 + half);
}
__device__ __forceinline__ int unpermc32(int p)
{
    int p5 = p & 31;
    int t = p5 >> 3, ks = (p5 & 7) >> 1, half = p5 & 1;
    return (p & ~31) | (ks * 8 + half * 4 + t);
}

__device__ __forceinline__ void mma_tf32(float* d, uint32_t a0, uint32_t a1,
                                         uint32_t a2, uint32_t a3,
                                         uint32_t b0, uint32_t b1)
{
    asm volatile(
        "mma.sync.aligned.m16n8k8.row.col.f32.tf32.tf32.f32 "
        "{%0,%1,%2,%3}, {%4,%5,%6,%7}, {%8,%9}, {%0,%1,%2,%3};"
        : "+f"(d[0]), "+f"(d[1]), "+f"(d[2]), "+f"(d[3])
        : "r"(a0), "r"(a1), "r"(a2), "r"(a3), "r"(b0), "r"(b1));
}

__device__ __forceinline__ void cpa16(uint32_t dst, const void* src)
{
    asm volatile("cp.async.cg.shared.global [%0], [%1], 16;"
                 :: "r"(dst), "l"(src));
}
#define CP_COMMIT() asm volatile("cp.async.commit_group;" ::: "memory")
#define CP_WAIT1()  asm volatile("cp.async.wait_group 1;" ::: "memory")

// ---------------- weight preprocessing: tf32 + permute ----------------
// m in 0..19 -> head h = m/5, sel = m%5 {q,k,v,l1,l2}
// rows always permuted (outputs). cols permuted when the GEMM input is in
// permuted space: everything except h==0 q/k/v.
__global__ void prep_w(const float* __restrict__ wq, const float* __restrict__ wk,
                       const float* __restrict__ wv, const float* __restrict__ wl1,
                       const float* __restrict__ wl2,
                       const float* __restrict__ bq, const float* __restrict__ bk,
                       const float* __restrict__ bv, const float* __restrict__ bl1,
                       const float* __restrict__ bl2,
                       float* __restrict__ wp, float* __restrict__ biasp)
{
    const int m = blockIdx.y;
    const int row = blockIdx.x;
    const int col = threadIdx.x;
    const int h = m / 5, sel = m % 5;
    const float* W; const float* B;
    switch (sel) {
        case 0: W = wq; B = bq; break;
        case 1: W = wk; B = bk; break;
        case 2: W = wv; B = bv; break;
        case 3: W = wl1; B = bl1; break;
        default: W = wl2; B = bl2; break;
    }
    const float v = W[(size_t)h * DD * DD + (size_t)row * DD + col];
    const int prow = permc32(row);
    const int pcol = (h > 0 || sel >= 3) ? permc32(col) : col;
    wp[(size_t)m * DD * DD + (size_t)prow * DD + pcol] = __uint_as_float(f2tf(v));
    if (row == 0)
        biasp[m * DD + permc32(col)] = B[h * DD + col];
}

// ---------------- GEMM ----------------
// C[M,256] = act(A)[M,256] @ Wp^T + biasp (output in permuted channel space)
// KPERM: smem k-order fully permuted -> LDS.128 fragment loads.
// CVTA: A is raw fp32, cvt to tf32 on fragment load (else pre-rounded).
// BN:   a' = relu(a*trs+trb) then cvt (implies KPERM).
// WOUT: wout = C - sub; STATS: column sum/sumsq atomics over (WOUT? wout : C).
// ROUND: round stored outputs to tf32.
template<bool KPERM, bool CVTA, bool BN, bool WOUT, bool STATS, bool ROUND>
__global__ __launch_bounds__(256, 2) void gemm_tc(
    const float* __restrict__ A, const float* __restrict__ Wp,
    const float* __restrict__ bias, float* __restrict__ C,
    const float* __restrict__ trs, const float* __restrict__ trb,
    const float* __restrict__ sub, float* __restrict__ wout,
    float* __restrict__ stats)
{
    extern __shared__ float sm[];
    const uint32_t smb = smem_u32(sm);

    const int tid = threadIdx.x;
    const int wid = tid >> 5, lane = tid & 31;
    const int g = lane >> 2, t = lane & 3;
    const int wm = wid >> 2;        // 0..1 (64 rows)
    const int wn = wid & 3;         // 0..3 (32 cols)
    const int row0 = blockIdx.y * BLKM;
    const int col0 = blockIdx.x * BLKN;

    // fill mapping: thread -> one half-row of 16 floats
    const int fr = tid >> 1, fk = (tid & 1) * 16;
    const float* const aptr = A + (size_t)(row0 + fr) * DD + fk;
    const float* const wptr = Wp + (size_t)(col0 + fr) * DD + fk;
    const uint32_t a_soff = (uint32_t)(fr * SA + fk) * 4u;
    const uint32_t b_soff = (uint32_t)(A_FL + fr * SA + fk) * 4u;

    float acc[4][4][4];
#pragma unroll
    for (int mt = 0; mt < 4; mt++)
#pragma unroll
        for (int nt = 0; nt < 4; nt++)
#pragma unroll
            for (int j = 0; j < 4; j++) acc[mt][nt][j] = 0.f;

    // prologue: chunks 0,1 into stages 0,1
#pragma unroll
    for (int p = 0; p < 2; p++) {
        const uint32_t sb = smb + (uint32_t)(p * STG_FL) * 4u;
        const float* ap = aptr + p * KCH;
        const float* wp2 = wptr + p * KCH;
#pragma unroll
        for (int j = 0; j < 4; j++) cpa16(sb + a_soff + j * 16, ap + j * 4);
#pragma unroll
        for (int j = 0; j < 4; j++) cpa16(sb + b_soff + j * 16, wp2 + j * 4);
        CP_COMMIT();
    }

#pragma unroll 1
    for (int i = 0; i < NCHUNK; i++) {
        CP_WAIT1();
        __syncthreads();

        // prefetch chunk i+2 (distance 2)
        if (i + 2 < NCHUNK) {
            const uint32_t sb = smb + (uint32_t)(((i + 2) % NSTAGE) * STG_FL) * 4u;
            const float* ap = aptr + (i + 2) * KCH;
            const float* wp2 = wptr + (i + 2) * KCH;
#pragma unroll
            for (int j = 0; j < 4; j++) cpa16(sb + a_soff + j * 16, ap + j * 4);
#pragma unroll
            for (int j = 0; j < 4; j++) cpa16(sb + b_soff + j * 16, wp2 + j * 4);
        }
        CP_COMMIT();

        const float* Ab = sm + (i % NSTAGE) * STG_FL;
        const float* Bb = Ab + A_FL;

        if (KPERM) {
            // two ks-pairs; per pair everything is contiguous LDS.128
#pragma unroll
            for (int p = 0; p < 2; p++) {
                float4 sv, cv;
                if (BN) {
                    sv = *(const float4*)(trs + i * KCH + t * 8 + p * 4);
                    cv = *(const float4*)(trb + i * KCH + t * 8 + p * 4);
                }
                uint32_t af[4][8];
#pragma unroll
                for (int mt = 0; mt < 4; mt++) {
                    const float* ap = Ab + (wm * 64 + mt * 16 + g) * SA + t * 8 + p * 4;
                    float4 lo = *(const float4*)ap;
                    float4 hi = *(const float4*)(ap + 8 * SA);
                    if (BN) {
                        lo.x = fmaxf(fmaf(lo.x, sv.x, cv.x), 0.f);
                        lo.y = fmaxf(fmaf(lo.y, sv.y, cv.y), 0.f);
                        lo.z = fmaxf(fmaf(lo.z, sv.z, cv.z), 0.f);
                        lo.w = fmaxf(fmaf(lo.w, sv.w, cv.w), 0.f);
                        hi.x = fmaxf(fmaf(hi.x, sv.x, cv.x), 0.f);
                        hi.y = fmaxf(fmaf(hi.y, sv.y, cv.y), 0.f);
                        hi.z = fmaxf(fmaf(hi.z, sv.z, cv.z), 0.f);
                        hi.w = fmaxf(fmaf(hi.w, sv.w, cv.w), 0.f);
                    }
                    if (BN || CVTA) {
                        af[mt][0] = f2tf(lo.x); af[mt][1] = f2tf(hi.x);
                        af[mt][2] = f2tf(lo.y); af[mt][3] = f2tf(hi.y);
                        af[mt][4] = f2tf(lo.z); af[mt][5] = f2tf(hi.z);
                        af[mt][6] = f2tf(lo.w); af[mt][7] = f2tf(hi.w);
                    } else {
                        af[mt][0] = __float_as_uint(lo.x); af[mt][1] = __float_as_uint(hi.x);
                        af[mt][2] = __float_as_uint(lo.y); af[mt][3] = __float_as_uint(hi.y);
                        af[mt][4] = __float_as_uint(lo.z); af[mt][5] = __float_as_uint(hi.z);
                        af[mt][6] = __float_as_uint(lo.w); af[mt][7] = __float_as_uint(hi.w);
                    }
                }
                uint32_t bf[4][4];
#pragma unroll
                for (int nt = 0; nt < 4; nt++) {
                    const float* bp = Bb + (wn * 32 + nt * 8 + g) * SA + t * 8 + p * 4;
                    float4 b = *(const float4*)bp;
                    bf[nt][0] = __float_as_uint(b.x);
                    bf[nt][1] = __float_as_uint(b.y);
                    bf[nt][2] = __float_as_uint(b.z);
                    bf[nt][3] = __float_as_uint(b.w);
                }
#pragma unroll
                for (int mt = 0; mt < 4; mt++)
#pragma unroll
                    for (int nt = 0; nt < 4; nt++) {
                        mma_tf32(acc[mt][nt], af[mt][0], af[mt][1], af[mt][2],
                                 af[mt][3], bf[nt][0], bf[nt][1]);
                        mma_tf32(acc[mt][nt], af[mt][4], af[mt][5], af[mt][6],
                                 af[mt][7], bf[nt][2], bf[nt][3]);
                    }
            }
        } else {
            // natural k-order (h==0 inputs): scalar fragment loads + cvt
#pragma unroll
            for (int ks = 0; ks < 4; ks++) {
                uint32_t af[4][4], bf[4][2];
#pragma unroll
                for (int mt = 0; mt < 4; mt++) {
                    const float* ap = Ab + (wm * 64 + mt * 16 + g) * SA + ks * 8;
                    float v0 = ap[t], v1 = ap[8 * SA + t];
                    float v2 = ap[t + 4], v3 = ap[8 * SA + t + 4];
                    af[mt][0] = f2tf(v0); af[mt][1] = f2tf(v1);
                    af[mt][2] = f2tf(v2); af[mt][3] = f2tf(v3);
                }
#pragma unroll
                for (int nt = 0; nt < 4; nt++) {
                    const float* bp = Bb + (wn * 32 + nt * 8 + g) * SA + ks * 8;
                    bf[nt][0] = __float_as_uint(bp[t]);
                    bf[nt][1] = __float_as_uint(bp[t + 4]);
                }
#pragma unroll
                for (int mt = 0; mt < 4; mt++)
#pragma unroll
                    for (int nt = 0; nt < 4; nt++)
                        mma_tf32(acc[mt][nt], af[mt][0], af[mt][1], af[mt][2],
                                 af[mt][3], bf[nt][0], bf[nt][1]);
            }
        }
    }

    // ---- epilogue ----
    float csum[8], csq[8];
    if (STATS) {
#pragma unroll
        for (int j = 0; j < 8; j++) { csum[j] = 0.f; csq[j] = 0.f; }
    }

#pragma unroll
    for (int mt = 0; mt < 4; mt++) {
        const int r = row0 + wm * 64 + mt * 16 + g;
#pragma unroll
        for (int nt = 0; nt < 4; nt++) {
            const int c = col0 + wn * 32 + nt * 8 + 2 * t;
            const float2 bi = *(const float2*)(bias + c);
            float2 o0, o1;
            o0.x = acc[mt][nt][0] + bi.x;
            o0.y = acc[mt][nt][1] + bi.y;
            o1.x = acc[mt][nt][2] + bi.x;
            o1.y = acc[mt][nt][3] + bi.y;
            if (ROUND) {
                o0.x = f2tff(o0.x); o0.y = f2tff(o0.y);
                o1.x = f2tff(o1.x); o1.y = f2tff(o1.y);
            }
            if (C != nullptr) {
                *(float2*)(C + (size_t)r * DD + c) = o0;
                *(float2*)(C + (size_t)(r + 8) * DD + c) = o1;
            }
            float2 v0 = o0, v1 = o1;
            if (WOUT) {
                float2 s0 = *(const float2*)(sub + (size_t)r * DD + c);
                float2 s1 = *(const float2*)(sub + (size_t)(r + 8) * DD + c);
                v0.x = o0.x - s0.x; v0.y = o0.y - s0.y;
                v1.x = o1.x - s1.x; v1.y = o1.y - s1.y;
                if (ROUND) {
                    v0.x = f2tff(v0.x); v0.y = f2tff(v0.y);
                    v1.x = f2tff(v1.x); v1.y = f2tff(v1.y);
                }
                *(float2*)(wout + (size_t)r * DD + c) = v0;
                *(float2*)(wout + (size_t)(r + 8) * DD + c) = v1;
            }
            if (STATS) {
                csum[nt * 2 + 0] += v0.x + v1.x;
                csum[nt * 2 + 1] += v0.y + v1.y;
                csq[nt * 2 + 0] += v0.x * v0.x + v1.x * v1.x;
                csq[nt * 2 + 1] += v0.y * v0.y + v1.y * v1.y;
            }
        }
    }

    if (STATS) {
#pragma unroll
        for (int j = 0; j < 8; j++) {
#pragma unroll
            for (int off = 4; off < 32; off <<= 1) {
                csum[j] += __shfl_xor_sync(0xFFFFFFFFu, csum[j], off);
                csq[j] += __shfl_xor_sync(0xFFFFFFFFu, csq[j], off);
            }
        }
        if (g == 0) {
#pragma unroll
            for (int nt = 0; nt < 4; nt++) {
#pragma unroll
                for (int j = 0; j < 2; j++) {
                    const int c = col0 + wn * 32 + nt * 8 + 2 * t + j;
                    atomicAdd(&stats[c], csum[nt * 2 + j]);
                    atomicAdd(&stats[256 + c], csq[nt * 2 + j]);
                }
            }
        }
    }
}

// ---------------- zero stats ----------------
__global__ void zero_stats_k(float* stats)
{
    stats[blockIdx.x * 512 + threadIdx.x] = 0.f;
}

// ---------------- BN finalize (permuted space) ----------------
__global__ void bn_finalize_k(const float* __restrict__ stats,
                              const float* __restrict__ gamma,
                              const float* __restrict__ beta,
                              float* __restrict__ scale, float* __restrict__ shift)
{
    const int p = threadIdx.x;
    const int c = unpermc32(p);
    const float invM = 1.0f / (float)MM;
    float mean = stats[p] * invM;
    float var = stats[256 + p] * invM - mean * mean;
    float sc = gamma[c] * rsqrtf(var + EPSV);
    scale[p] = sc;
    shift[p] = beta[c] - mean * sc;
}

// ---------------- fused softmax(seq) * v sum (permuted in, natural out) ----------------
__global__ __launch_bounds__(256) void softmax_wv_k(const float* __restrict__ w,
                                                    const float* __restrict__ v,
                                                    float* __restrict__ xcat, int head)
{
    const int c = blockIdx.x * 32 + threadIdx.x;   // permuted-space column
    const int ty = threadIdx.y;
    float m = -1e30f, l = 0.f, a = 0.f;
    for (int s = ty; s < SS; s += 8) {
        const size_t idx = (size_t)s * (BB * DD) + c;
        float x = w[idx];
        float val = v[idx];
        float nm = fmaxf(m, x);
        float corr = __expf(m - nm);
        float e = __expf(x - nm);
        l = l * corr + e;
        a = a * corr + e * val;
        m = nm;
    }
    __shared__ float sm_[8][32], sl[8][32], sa[8][32];
    sm_[ty][threadIdx.x] = m;
    sl[ty][threadIdx.x] = l;
    sa[ty][threadIdx.x] = a;
    __syncthreads();
    if (ty == 0) {
        for (int j = 1; j < 8; j++) {
            float m2 = sm_[j][threadIdx.x], l2 = sl[j][threadIdx.x], a2 = sa[j][threadIdx.x];
            float nm = fmaxf(m, m2);
            float c1 = __expf(m - nm), c2 = __expf(m2 - nm);
            l = l * c1 + l2 * c2;
            a = a * c1 + a2 * c2;
            m = nm;
        }
        const int b = c >> 8;
        const int d = unpermc32(c & 255);   // back to natural channel
        xcat[b * (DD * HH) + head * DD + d] = a / l;
    }
}

// ---------------- tiny final MLP layer ----------------
__global__ __launch_bounds__(256) void mlp_k(const float* __restrict__ x,
                                             const float* __restrict__ Wt,
                                             const float* __restrict__ bias,
                                             float* __restrict__ y, int K, int do_relu)
{
    __shared__ float xs[1024];
    const int b = blockIdx.x;
    for (int i = threadIdx.x; i < K; i += 256) xs[i] = x[b * K + i];
    __syncthreads();
    const int n = threadIdx.x;
    float acc = bias[n];
    const float* wr = Wt + (size_t)n * K;
    for (int k = 0; k < K; k++) acc = fmaf(xs[k], wr[k], acc);
    if (do_relu) acc = fmaxf(acc, 0.f);
    y[b * DD + n] = acc;
}

// ---------------- driver ----------------
static float* sym(const void* s)
{
    void* p = nullptr;
    cudaGetSymbolAddress(&p, (const void*)s);
    return (float*)p;
}

extern "C" void kernel_launch(void* const* d_in, const int* in_sizes, int n_in,
                              void* d_out, int out_size)
{
    (void)in_sizes; (void)n_in; (void)out_size;
    const float* q_in = (const float*)d_in[0];
    const float* k_in = (const float*)d_in[1];
    const float* v_in = (const float*)d_in[2];
    const float* wq = (const float*)d_in[3];
    const float* bq = (const float*)d_in[4];
    const float* wk = (const float*)d_in[5];
    const float* bk = (const float*)d_in[6];
    const float* wv = (const float*)d_in[7];
    const float* bv = (const float*)d_in[8];
    const float* g1 = (const float*)d_in[9];
    const float* be1 = (const float*)d_in[10];
    const float* wl1 = (const float*)d_in[11];
    const float* bl1 = (const float*)d_in[12];
    const float* g2 = (const float*)d_in[13];
    const float* be2 = (const float*)d_in[14];
    const float* wl2 = (const float*)d_in[15];
    const float* bl2 = (const float*)d_in[16];
    const float* mw0 = (const float*)d_in[17];
    const float* mb0 = (const float*)d_in[18];
    const float* mw1 = (const float*)d_in[19];
    const float* mb1 = (const float*)d_in[20];
    const float* mw2 = (const float*)d_in[21];
    const float* mb2 = (const float*)d_in[22];

    float* qa = sym(g_qa); float* qb = sym(g_qb);
    float* ka = sym(g_ka); float* kb = sym(g_kb);
    float* va = sym(g_va); float* vb = sym(g_vb);
    float* w1 = sym(g_w1); float* w2 = sym(g_w2);
    float* wp = sym(g_wp);
    float* biasp = sym(g_biasp);
    float* stats8 = sym(g_stats8);
    float* scale8 = sym(g_scale);
    float* shift8 = sym(g_shift);
    float* xcat = sym(g_xcat);
    float* m0 = sym(g_m0);
    float* m1 = sym(g_m1);

    // instantiations:
    //   h0 q/v : KPERM=0 CVTA=1 BN=0 WOUT=0 STATS=0 ROUND=1
    //   h0 k   : KPERM=0 CVTA=1 BN=0 WOUT=1 STATS=1 ROUND=1
    //   h>0 q/v: KPERM=1 CVTA=0 BN=0 WOUT=0 STATS=0 ROUND=1
    //   h>0 k  : KPERM=1 CVTA=0 BN=0 WOUT=1 STATS=1 ROUND=1
    //   l1     : KPERM=1 CVTA=0 BN=1 WOUT=0 STATS=1 ROUND=1
    //   l2     : KPERM=1 CVTA=0 BN=1 WOUT=0 STATS=0 ROUND=0
    auto* Gh0qv = gemm_tc<false, true, false, false, false, true>;
    auto* Gh0k  = gemm_tc<false, true, false, true, true, true>;
    auto* Gqv   = gemm_tc<true, false, false, false, false, true>;
    auto* Gk    = gemm_tc<true, false, false, true, true, true>;
    auto* Gl1   = gemm_tc<true, false, true, false, true, true>;
    auto* Gl2   = gemm_tc<true, false, true, false, false, false>;

    cudaFuncSetAttribute(Gh0qv, cudaFuncAttributeMaxDynamicSharedMemorySize, SMEM_BYTES);
    cudaFuncSetAttribute(Gh0k, cudaFuncAttributeMaxDynamicSharedMemorySize, SMEM_BYTES);
    cudaFuncSetAttribute(Gqv, cudaFuncAttributeMaxDynamicSharedMemorySize, SMEM_BYTES);
    cudaFuncSetAttribute(Gk, cudaFuncAttributeMaxDynamicSharedMemorySize, SMEM_BYTES);
    cudaFuncSetAttribute(Gl1, cudaFuncAttributeMaxDynamicSharedMemorySize, SMEM_BYTES);
    cudaFuncSetAttribute(Gl2, cudaFuncAttributeMaxDynamicSharedMemorySize, SMEM_BYTES);

    // preprocess weights + biases (tf32, permuted) and zero stats
    prep_w<<<dim3(DD, 20), DD>>>(wq, wk, wv, wl1, wl2, bq, bk, bv, bl1, bl2,
                                 wp, biasp);
    zero_stats_k<<<8, 512>>>(stats8);

    const dim3 gg(DD / BLKN, MM / BLKM);   // (2, 512)
    const float* qs = q_in; const float* ks = k_in; const float* vs = v_in;
    float* qpp[2] = { qa, qb };
    float* kpp[2] = { ka, kb };
    float* vpp[2] = { va, vb };

    for (int h = 0; h < HH; h++) {
        float* qd = qpp[h & 1];
        float* kd = kpp[h & 1];
        float* vd = vpp[h & 1];
        const int mq = h * 5 + 0, mk = h * 5 + 1, mv = h * 5 + 2;
        const int ml1 = h * 5 + 3, ml2 = h * 5 + 4;
        const float* Wq = wp + (size_t)mq * DD * DD;
        const float* Wk = wp + (size_t)mk * DD * DD;
        const float* Wv = wp + (size_t)mv * DD * DD;
        const float* Wm1 = wp + (size_t)ml1 * DD * DD;
        const float* Wm2 = wp + (size_t)ml2 * DD * DD;
        float* st1 = stats8 + (size_t)(2 * h) * 512;
        float* st2 = stats8 + (size_t)(2 * h + 1) * 512;
        float* sc1 = scale8 + (size_t)(2 * h) * 256;
        float* sh1 = shift8 + (size_t)(2 * h) * 256;
        float* sc2 = scale8 + (size_t)(2 * h + 1) * 256;
        float* sh2 = shift8 + (size_t)(2 * h + 1) * 256;

        if (h == 0) {
            Gh0qv<<<gg, 256, SMEM_BYTES>>>(
                qs, Wq, biasp + mq * DD, qd, nullptr, nullptr, nullptr, nullptr,
                nullptr);
            Gh0qv<<<gg, 256, SMEM_BYTES>>>(
                vs, Wv, biasp + mv * DD, vd, nullptr, nullptr, nullptr, nullptr,
                nullptr);
            Gh0k<<<gg, 256, SMEM_BYTES>>>(
                ks, Wk, biasp + mk * DD, kd, nullptr, nullptr, qd, w1, st1);
        } else {
            Gqv<<<gg, 256, SMEM_BYTES>>>(
                qs, Wq, biasp + mq * DD, qd, nullptr, nullptr, nullptr, nullptr,
                nullptr);
            Gqv<<<gg, 256, SMEM_BYTES>>>(
                vs, Wv, biasp + mv * DD, vd, nullptr, nullptr, nullptr, nullptr,
                nullptr);
            Gk<<<gg, 256, SMEM_BYTES>>>(
                ks, Wk, biasp + mk * DD, (h == HH - 1) ? nullptr : kd,
                nullptr, nullptr, qd, w1, st1);
        }

        bn_finalize_k<<<1, 256>>>(st1, g1 + h * DD, be1 + h * DD, sc1, sh1);
        Gl1<<<gg, 256, SMEM_BYTES>>>(
            w1, Wm1, biasp + ml1 * DD, w2, sc1, sh1, nullptr, nullptr, st2);

        bn_finalize_k<<<1, 256>>>(st2, g2 + h * DD, be2 + h * DD, sc2, sh2);
        Gl2<<<gg, 256, SMEM_BYTES>>>(
            w2, Wm2, biasp + ml2 * DD, w1, sc2, sh2, nullptr, nullptr, nullptr);

        softmax_wv_k<<<256, dim3(32, 8)>>>(w1, vd, xcat, h);

        qs = qd; ks = kd; vs = vd;
    }

    mlp_k<<<BB, 256>>>(xcat, mw0, mb0, m0, DD * HH, 1);
    mlp_k<<<BB, 256>>>(m0, mw1, mb1, m1, DD, 1);
    mlp_k<<<BB, 256>>>(m1, mw2, mb2, (float*)d_out, DD, 0);
}